// round 7
// baseline (speedup 1.0000x reference)
#include <cuda_runtime.h>
#include <cuda_bf16.h>
#include <math.h>

// ---------------- problem constants ----------------
#define T_    2048
#define D_    2048
#define NQ_   16
#define NKV_  4
#define H_    128
#define E_    16
#define F_    1024
#define TOPK_ 4
#define EPS_  1e-6f
#define SCALE_ 0.088388347648318447f  // 128^-0.5

// ---------------- scratch (device globals; no allocation allowed) ----------------
__device__ float g_hnorm [(size_t)T_ * D_];
__device__ float g_q     [(size_t)T_ * NQ_ * H_];
__device__ float g_k     [(size_t)T_ * NKV_ * H_];
__device__ float g_v     [(size_t)T_ * NKV_ * H_];
__device__ float g_attnout[(size_t)T_ * NQ_ * H_];
__device__ float g_hres  [(size_t)T_ * D_];
__device__ float g_h2    [(size_t)T_ * D_];
__device__ float g_gated [(size_t)T_ * TOPK_ * F_];
__device__ float g_pairout[(size_t)T_ * TOPK_ * D_];

__device__ int   g_topidx[T_ * TOPK_];
__device__ float g_topw  [T_ * TOPK_];
__device__ int   g_counts[E_];
__device__ int   g_offsets[E_];
__device__ int   g_cursor[E_];
__device__ int   g_pair_token[T_ * TOPK_];
__device__ int   g_pair_slot [T_ * TOPK_];

// ---------------- mma / cp.async helpers ----------------
__device__ __forceinline__ void mma_tf32(float* d, const unsigned* a, const unsigned* b) {
    asm volatile(
        "mma.sync.aligned.m16n8k8.row.col.f32.tf32.tf32.f32 "
        "{%0,%1,%2,%3},{%4,%5,%6,%7},{%8,%9},{%0,%1,%2,%3};\n"
        : "+f"(d[0]), "+f"(d[1]), "+f"(d[2]), "+f"(d[3])
        : "r"(a[0]), "r"(a[1]), "r"(a[2]), "r"(a[3]), "r"(b[0]), "r"(b[1]));
}
__device__ __forceinline__ void cpa16(void* smem, const void* g) {
    unsigned s = (unsigned)__cvta_generic_to_shared(smem);
    asm volatile("cp.async.cg.shared.global [%0], [%1], 16;\n" :: "r"(s), "l"(g));
}
__device__ __forceinline__ void cpa_commit() {
    asm volatile("cp.async.commit_group;\n");
}
__device__ __forceinline__ void cpa_wait0() {
    asm volatile("cp.async.wait_group 0;\n");
}

// ---------------- generic tf32 GEMM (NN): BK=32, 2-stage, 1 barrier/iter --------
// Tile 128x128, 256 threads (8 warps as 2x4, warp 64x32). Dynamic smem, 2 CTA/SM.
#define AS_LD 36
#define BS_LD 136
#define GEMM_SMEM ((2 * 128 * AS_LD + 2 * 32 * BS_LD) * 4)
__device__ __forceinline__ void gemm_tf32_body(
    float* dsm,
    const float* __restrict__ A, int lda,
    const float* __restrict__ B, int ldb,
    float* __restrict__ C, int ldc,
    int n0, int K, const float* __restrict__ resid, int mlimit)
{
    float* As = dsm;                        // [2][128][AS_LD]
    float* Bs = dsm + 2 * 128 * AS_LD;      // [2][32][BS_LD]
    const int m0 = blockIdx.y * 128;
    const int tid = threadIdx.x, lane = tid & 31, warp = tid >> 5;
    const int wm = warp >> 2, wn = warp & 3;
    const int gid = lane >> 2, tq = lane & 3;
    float acc[4][4][4] = {};

    // A: 128 rows x 32 cols/stage = 1024 float4; 4 per thread
    const int ar0 = tid >> 1;                  // 0..127
    const int ac0 = (tid & 1) * 16;            // 0 or 16 (+0,4,8,12)
    int arow = m0 + ar0; if (arow >= mlimit) arow = mlimit - 1;
    // B: 32 rows x 128 cols/stage = 1024 float4; 4 per thread
    const int br0 = tid >> 5;                  // 0..7 (+0,8,16,24)
    const int bc0 = (tid & 31) * 4;

    const int niter = K >> 5;
    auto issue = [&](int it) {
        int k0 = it << 5;
        float* as = As + (it & 1) * 128 * AS_LD;
        float* bs = Bs + (it & 1) * 32 * BS_LD;
        #pragma unroll
        for (int u = 0; u < 4; u++)
            cpa16(&as[ar0 * AS_LD + ac0 + u * 4], &A[(size_t)arow * lda + k0 + ac0 + u * 4]);
        #pragma unroll
        for (int u = 0; u < 4; u++)
            cpa16(&bs[(br0 + u * 8) * BS_LD + bc0], &B[(size_t)(k0 + br0 + u * 8) * ldb + n0 + bc0]);
        cpa_commit();
    };
    issue(0);

    for (int it = 0; it < niter; it++) {
        cpa_wait0();
        __syncthreads();
        if (it + 1 < niter) issue(it + 1);
        const float* as = As + (it & 1) * 128 * AS_LD;
        const float* bs = Bs + (it & 1) * 32 * BS_LD;
        #pragma unroll
        for (int ks = 0; ks < 32; ks += 8) {
            unsigned a[4][4], b[4][2];
            #pragma unroll
            for (int tm = 0; tm < 4; tm++) {
                int r0 = wm * 64 + tm * 16 + gid;
                a[tm][0] = __float_as_uint(as[r0 * AS_LD + ks + tq]);
                a[tm][1] = __float_as_uint(as[(r0 + 8) * AS_LD + ks + tq]);
                a[tm][2] = __float_as_uint(as[r0 * AS_LD + ks + tq + 4]);
                a[tm][3] = __float_as_uint(as[(r0 + 8) * AS_LD + ks + tq + 4]);
            }
            #pragma unroll
            for (int tn = 0; tn < 4; tn++) {
                int c = wn * 32 + tn * 8 + gid;
                b[tn][0] = __float_as_uint(bs[(ks + tq) * BS_LD + c]);
                b[tn][1] = __float_as_uint(bs[(ks + tq + 4) * BS_LD + c]);
            }
            #pragma unroll
            for (int tm = 0; tm < 4; tm++)
                #pragma unroll
                for (int tn = 0; tn < 4; tn++)
                    mma_tf32(acc[tm][tn], a[tm], b[tn]);
        }
    }
    __syncthreads();
    #pragma unroll
    for (int tm = 0; tm < 4; tm++) {
        int r0 = m0 + wm * 64 + tm * 16 + gid;
        int r1 = r0 + 8;
        #pragma unroll
        for (int tn = 0; tn < 4; tn++) {
            int c0 = n0 + wn * 32 + tn * 8 + 2 * tq;
            if (r0 < mlimit) {
                float v0 = acc[tm][tn][0], v1 = acc[tm][tn][1];
                if (resid) { v0 += resid[(size_t)r0 * ldc + c0]; v1 += resid[(size_t)r0 * ldc + c0 + 1]; }
                C[(size_t)r0 * ldc + c0] = v0; C[(size_t)r0 * ldc + c0 + 1] = v1;
            }
            if (r1 < mlimit) {
                float v2 = acc[tm][tn][2], v3 = acc[tm][tn][3];
                if (resid) { v2 += resid[(size_t)r1 * ldc + c0]; v3 += resid[(size_t)r1 * ldc + c0 + 1]; }
                C[(size_t)r1 * ldc + c0] = v2; C[(size_t)r1 * ldc + c0 + 1] = v3;
            }
        }
    }
}

// ---------------- kernels ----------------

__global__ void k_rmsnorm(const float* __restrict__ x_ext,
                          const float* __restrict__ w, int mode)
{
    const int t = blockIdx.x;
    const float* px = (mode == 0) ? (x_ext + (size_t)t * D_) : (g_hres + (size_t)t * D_);
    float* py = (mode == 0) ? (g_hnorm + (size_t)t * D_) : (g_h2 + (size_t)t * D_);
    float ss = 0.f;
    for (int d = threadIdx.x; d < D_; d += 256) { float v = px[d]; ss += v * v; }
    __shared__ float red[256];
    red[threadIdx.x] = ss; __syncthreads();
    for (int s = 128; s > 0; s >>= 1) {
        if (threadIdx.x < s) red[threadIdx.x] += red[threadIdx.x + s];
        __syncthreads();
    }
    float r = rsqrtf(red[0] / D_ + EPS_);
    for (int d = threadIdx.x; d < D_; d += 256) py[d] = px[d] * r * w[d];
}

// fused QKV projection: blockIdx.x 0..15 -> q tile, 16..19 -> k, 20..23 -> v
__global__ void __launch_bounds__(256, 2) k_qkv(const float* __restrict__ qw,
                                                const float* __restrict__ kw,
                                                const float* __restrict__ vw)
{
    extern __shared__ float dsm[];
    const int bx = blockIdx.x;
    if (bx < 16) {
        gemm_tf32_body(dsm, g_hnorm, D_, qw, NQ_ * H_, g_q, NQ_ * H_, bx * 128, D_, nullptr, T_);
    } else if (bx < 20) {
        gemm_tf32_body(dsm, g_hnorm, D_, kw, NKV_ * H_, g_k, NKV_ * H_, (bx - 16) * 128, D_, nullptr, T_);
    } else {
        gemm_tf32_body(dsm, g_hnorm, D_, vw, NKV_ * H_, g_v, NKV_ * H_, (bx - 20) * 128, D_, nullptr, T_);
    }
}

__global__ void k_normrope(const float* __restrict__ w,
                           const float* __restrict__ cs,
                           const float* __restrict__ sn, int which)
{
    const int t = blockIdx.x, n = blockIdx.y, d = threadIdx.x; // 128 threads
    float* base = (which == 0) ? g_q : g_k;
    int nh = (which == 0) ? NQ_ : NKV_;
    float* p = base + (size_t)t * nh * H_ + (size_t)n * H_;
    float v = p[d];
    __shared__ float sh[128];
    sh[d] = v * v; __syncthreads();
    for (int s = 64; s > 0; s >>= 1) {
        if (d < s) sh[d] += sh[d + s];
        __syncthreads();
    }
    float r = rsqrtf(sh[0] / H_ + EPS_);
    __syncthreads();
    float xn = v * r * w[d];
    sh[d] = xn; __syncthreads();
    float rot = (d < 64) ? -sh[d + 64] : sh[d - 64];
    p[d] = xn * cs[(size_t)t * H_ + d] + rot * sn[(size_t)t * H_ + d];
}

// ---------------- flash attention with tf32 mma ----------------
#define FKV_LD 132
#define FPS_LD 68
#define FA_SMEM ((64 * FKV_LD + 2 * 64 * FKV_LD + 2 * 64 * FKV_LD + 64 * FPS_LD + 3 * 64) * 4)

__global__ void __launch_bounds__(256) k_flashattn()
{
    extern __shared__ float sm[];
    float* Qs    = sm;
    float* Ks    = Qs + 64 * FKV_LD;
    float* Vs    = Ks + 2 * 64 * FKV_LD;
    float* Ps    = Vs + 2 * 64 * FKV_LD;
    float* m_s   = Ps + 64 * FPS_LD;
    float* l_s   = m_s + 64;
    float* fac_s = l_s + 64;

    const int by = blockIdx.x;
    const int n  = blockIdx.y;
    const int kv = n >> 2;
    const int tid = threadIdx.x, lane = tid & 31, warp = tid >> 5;
    const int wm = warp >> 1, wn = warp & 1;
    const int gid = lane >> 2, tq = lane & 3;
    const int m0 = by * 64;

    #pragma unroll
    for (int i = 0; i < 8; i++) {
        int idx = tid + 256 * i;
        int r = idx >> 5, c4 = (idx & 31) * 4;
        cpa16(&Qs[r * FKV_LD + c4], &g_q[((size_t)(m0 + r) * NQ_ + n) * H_ + c4]);
    }
    if (tid < 64) { m_s[tid] = -1e30f; l_s[tid] = 0.f; }

    auto issue_kv = [&](int kt, int buf) {
        int s0 = kt * 64;
        float* kd = Ks + buf * 64 * FKV_LD;
        float* vd = Vs + buf * 64 * FKV_LD;
        #pragma unroll
        for (int i = 0; i < 8; i++) {
            int idx = tid + 256 * i;
            int r = idx >> 5, c4 = (idx & 31) * 4;
            cpa16(&kd[r * FKV_LD + c4], &g_k[((size_t)(s0 + r) * NKV_ + kv) * H_ + c4]);
            cpa16(&vd[r * FKV_LD + c4], &g_v[((size_t)(s0 + r) * NKV_ + kv) * H_ + c4]);
        }
        cpa_commit();
    };
    issue_kv(0, 0);

    float o[8][4] = {};

    for (int kt = 0; kt <= by; kt++) {
        cpa_wait0();
        __syncthreads();
        if (kt < by) issue_kv(kt + 1, (kt + 1) & 1);

        const float* K = Ks + (kt & 1) * 64 * FKV_LD;
        const float* V = Vs + (kt & 1) * 64 * FKV_LD;

        float s[4][4] = {};
        #pragma unroll
        for (int ks = 0; ks < H_; ks += 8) {
            unsigned a[4], b[4][2];
            int r0 = wm * 16 + gid;
            a[0] = __float_as_uint(Qs[r0 * FKV_LD + ks + tq]);
            a[1] = __float_as_uint(Qs[(r0 + 8) * FKV_LD + ks + tq]);
            a[2] = __float_as_uint(Qs[r0 * FKV_LD + ks + tq + 4]);
            a[3] = __float_as_uint(Qs[(r0 + 8) * FKV_LD + ks + tq + 4]);
            #pragma unroll
            for (int f = 0; f < 4; f++) {
                int c = wn * 32 + f * 8 + gid;
                b[f][0] = __float_as_uint(K[c * FKV_LD + ks + tq]);
                b[f][1] = __float_as_uint(K[c * FKV_LD + ks + tq + 4]);
            }
            #pragma unroll
            for (int f = 0; f < 4; f++) mma_tf32(s[f], a, b[f]);
        }
        {
            int r0 = wm * 16 + gid;
            #pragma unroll
            for (int f = 0; f < 4; f++) {
                int c = wn * 32 + f * 8 + 2 * tq;
                float v0 = s[f][0] * SCALE_, v1 = s[f][1] * SCALE_;
                float v2 = s[f][2] * SCALE_, v3 = s[f][3] * SCALE_;
                if (kt == by) {
                    if (c     > r0)     v0 = -1e30f;
                    if (c + 1 > r0)     v1 = -1e30f;
                    if (c     > r0 + 8) v2 = -1e30f;
                    if (c + 1 > r0 + 8) v3 = -1e30f;
                }
                Ps[r0 * FPS_LD + c] = v0;       Ps[r0 * FPS_LD + c + 1] = v1;
                Ps[(r0 + 8) * FPS_LD + c] = v2; Ps[(r0 + 8) * FPS_LD + c + 1] = v3;
            }
        }
        __syncthreads();

        {
            int row = tid >> 2, sub = tid & 3;
            float* pr = Ps + row * FPS_LD + sub * 16;
            float mx = -1e30f;
            #pragma unroll
            for (int i = 0; i < 16; i++) mx = fmaxf(mx, pr[i]);
            mx = fmaxf(mx, __shfl_xor_sync(0xffffffffu, mx, 1));
            mx = fmaxf(mx, __shfl_xor_sync(0xffffffffu, mx, 2));
            float mold = m_s[row];
            float lold = l_s[row];
            float mnew = fmaxf(mold, mx);
            float fac = __expf(mold - mnew);
            float sum = 0.f;
            #pragma unroll
            for (int i = 0; i < 16; i++) {
                float p = __expf(pr[i] - mnew);
                pr[i] = p; sum += p;
            }
            sum += __shfl_xor_sync(0xffffffffu, sum, 1);
            sum += __shfl_xor_sync(0xffffffffu, sum, 2);
            m_s[row] = mnew;
            l_s[row] = lold * fac + sum;
            fac_s[row] = fac;
        }
        __syncthreads();

        {
            float f0 = fac_s[wm * 16 + gid], f1 = fac_s[wm * 16 + gid + 8];
            #pragma unroll
            for (int f = 0; f < 8; f++) {
                o[f][0] *= f0; o[f][1] *= f0; o[f][2] *= f1; o[f][3] *= f1;
            }
        }

        #pragma unroll
        for (int ks = 0; ks < 64; ks += 8) {
            unsigned a[4];
            int r0 = wm * 16 + gid;
            a[0] = __float_as_uint(Ps[r0 * FPS_LD + ks + tq]);
            a[1] = __float_as_uint(Ps[(r0 + 8) * FPS_LD + ks + tq]);
            a[2] = __float_as_uint(Ps[r0 * FPS_LD + ks + tq + 4]);
            a[3] = __float_as_uint(Ps[(r0 + 8) * FPS_LD + ks + tq + 4]);
            #pragma unroll
            for (int f = 0; f < 8; f++) {
                unsigned b[2];
                int c = wn * 64 + f * 8 + gid;
                b[0] = __float_as_uint(V[(ks + tq) * FKV_LD + c]);
                b[1] = __float_as_uint(V[(ks + tq + 4) * FKV_LD + c]);
                mma_tf32(o[f], a, b);
            }
        }
    }

    {
        float inv0 = 1.f / l_s[wm * 16 + gid];
        float inv1 = 1.f / l_s[wm * 16 + gid + 8];
        int r0 = m0 + wm * 16 + gid;
        int r1 = r0 + 8;
        #pragma unroll
        for (int f = 0; f < 8; f++) {
            int c = wn * 64 + f * 8 + 2 * tq;
            float* d0 = &g_attnout[((size_t)r0 * NQ_ + n) * H_ + c];
            float* d1 = &g_attnout[((size_t)r1 * NQ_ + n) * H_ + c];
            d0[0] = o[f][0] * inv0; d0[1] = o[f][1] * inv0;
            d1[0] = o[f][2] * inv1; d1[1] = o[f][3] * inv1;
        }
    }
}

__global__ void __launch_bounds__(256, 2) k_oproj(const float* __restrict__ W,
                                                  const float* __restrict__ resid)
{
    extern __shared__ float dsm[];
    gemm_tf32_body(dsm, g_attnout, NQ_ * H_, W, D_, g_hres, D_,
                   blockIdx.x * 128, NQ_ * H_, resid, T_);
}

__global__ void k_zero()
{
    if (threadIdx.x < E_) g_counts[threadIdx.x] = 0;
}

__global__ void k_router(const float* __restrict__ gate_w)
{
    const int t = blockIdx.x, tid = threadIdx.x; // 128 threads
    const float* x = g_h2 + (size_t)t * D_;
    float acc[E_];
    #pragma unroll
    for (int e = 0; e < E_; e++) acc[e] = 0.f;
    for (int d = tid; d < D_; d += 128) {
        float xv = x[d];
        const float* gw = gate_w + (size_t)d * E_;
        #pragma unroll
        for (int e = 0; e < E_; e++) acc[e] = fmaf(xv, gw[e], acc[e]);
    }
    __shared__ float sh[128 * E_];
    #pragma unroll
    for (int e = 0; e < E_; e++) sh[tid * E_ + e] = acc[e];
    __syncthreads();
    for (int s = 64; s > 0; s >>= 1) {
        if (tid < s)
            #pragma unroll
            for (int e = 0; e < E_; e++) sh[tid * E_ + e] += sh[(tid + s) * E_ + e];
        __syncthreads();
    }
    if (tid == 0) {
        float p[E_];
        float m = -1e30f;
        for (int e = 0; e < E_; e++) m = fmaxf(m, sh[e]);
        float sum = 0.f;
        for (int e = 0; e < E_; e++) { p[e] = __expf(sh[e] - m); sum += p[e]; }
        float invs = 1.f / sum;
        for (int e = 0; e < E_; e++) p[e] *= invs;
        int idx[TOPK_]; float wv[TOPK_]; float wsum = 0.f;
        for (int k = 0; k < TOPK_; k++) {
            int best = 0; float bv = p[0];
            for (int e = 1; e < E_; e++) if (p[e] > bv) { bv = p[e]; best = e; }
            idx[k] = best; wv[k] = bv; wsum += bv; p[best] = -1.f;
        }
        float invw = 1.f / wsum;
        for (int k = 0; k < TOPK_; k++) {
            g_topidx[t * TOPK_ + k] = idx[k];
            g_topw[t * TOPK_ + k] = wv[k] * invw;
            atomicAdd(&g_counts[idx[k]], 1);
        }
    }
}

__global__ void k_scan()
{
    int off = 0;
    for (int e = 0; e < E_; e++) {
        g_offsets[e] = off;
        off += g_counts[e];
        g_cursor[e] = 0;
    }
}

__global__ void k_assign()
{
    int i = blockIdx.x * blockDim.x + threadIdx.x;
    if (i >= T_ * TOPK_) return;
    int e = g_topidx[i];
    int slot = g_offsets[e] + atomicAdd(&g_cursor[e], 1);
    g_pair_token[slot] = i >> 2;
    g_pair_slot[i] = slot;
}

// ---------------- MoE gate_up: BK=32, 2-stage, 1 barrier/iter --------------------
#define BGU_LD 72
#define GU_SMEM ((2 * 128 * AS_LD + 2 * 2 * 32 * BGU_LD) * 4)
__global__ void __launch_bounds__(256, 2) k_gateup(const float* __restrict__ gate_up_w)
{
    extern __shared__ float dsm[];
    float* As = dsm;                                 // [2][128][AS_LD]
    float* Bg = dsm + 2 * 128 * AS_LD;               // [2][32][BGU_LD]
    float* Bu = Bg + 2 * 32 * BGU_LD;                // [2][32][BGU_LD]
    __shared__ int rowTok[128];

    const int e = blockIdx.z;
    const int cnt = g_counts[e];
    const int m0 = blockIdx.y * 128;
    if (m0 >= cnt) return;
    const int base = g_offsets[e];
    const int n0 = blockIdx.x * 64;
    const float* B = gate_up_w + (size_t)e * D_ * (2 * F_);

    const int tid = threadIdx.x, lane = tid & 31, warp = tid >> 5;
    const int wm = warp >> 2, wn = warp & 3;
    const int gid = lane >> 2, tq = lane & 3;

    if (tid < 128) {
        int r = m0 + tid;
        rowTok[tid] = (r < cnt) ? g_pair_token[base + r] : g_pair_token[base];
    }
    __syncthreads();

    const int ar0 = tid >> 1;
    const int ac0 = (tid & 1) * 16;
    const size_t arow = (size_t)rowTok[ar0] * D_;
    const int br0 = tid >> 4;          // 0..15 (+0,16)
    const int bc0 = (tid & 15) * 4;    // 0..60

    float ag[4][2][4] = {}, au[4][2][4] = {};

    const int niter = D_ >> 5;
    auto issue = [&](int it) {
        int k0 = it << 5;
        float* as = As + (it & 1) * 128 * AS_LD;
        float* bgp = Bg + (it & 1) * 32 * BGU_LD;
        float* bup = Bu + (it & 1) * 32 * BGU_LD;
        #pragma unroll
        for (int u = 0; u < 4; u++)
            cpa16(&as[ar0 * AS_LD + ac0 + u * 4], &g_h2[arow + k0 + ac0 + u * 4]);
        #pragma unroll
        for (int u = 0; u < 2; u++) {
            const float* brow = B + (size_t)(k0 + br0 + u * 16) * (2 * F_);
            cpa16(&bgp[(br0 + u * 16) * BGU_LD + bc0], &brow[n0 + bc0]);
            cpa16(&bup[(br0 + u * 16) * BGU_LD + bc0], &brow[F_ + n0 + bc0]);
        }
        cpa_commit();
    };
    issue(0);

    for (int it = 0; it < niter; it++) {
        cpa_wait0();
        __syncthreads();
        if (it + 1 < niter) issue(it + 1);
        const float* as = As + (it & 1) * 128 * AS_LD;
        const float* bgp = Bg + (it & 1) * 32 * BGU_LD;
        const float* bup = Bu + (it & 1) * 32 * BGU_LD;
        #pragma unroll
        for (int ks = 0; ks < 32; ks += 8) {
            unsigned a[4][4], bg[2][2], bu[2][2];
            #pragma unroll
            for (int tm = 0; tm < 4; tm++) {
                int r0 = wm * 64 + tm * 16 + gid;
                a[tm][0] = __float_as_uint(as[r0 * AS_LD + ks + tq]);
                a[tm][1] = __float_as_uint(as[(r0 + 8) * AS_LD + ks + tq]);
                a[tm][2] = __float_as_uint(as[r0 * AS_LD + ks + tq + 4]);
                a[tm][3] = __float_as_uint(as[(r0 + 8) * AS_LD + ks + tq + 4]);
            }
            #pragma unroll
            for (int tn = 0; tn < 2; tn++) {
                int c = wn * 16 + tn * 8 + gid;
                bg[tn][0] = __float_as_uint(bgp[(ks + tq) * BGU_LD + c]);
                bg[tn][1] = __float_as_uint(bgp[(ks + tq + 4) * BGU_LD + c]);
                bu[tn][0] = __float_as_uint(bup[(ks + tq) * BGU_LD + c]);
                bu[tn][1] = __float_as_uint(bup[(ks + tq + 4) * BGU_LD + c]);
            }
            #pragma unroll
            for (int tm = 0; tm < 4; tm++)
                #pragma unroll
                for (int tn = 0; tn < 2; tn++) {
                    mma_tf32(ag[tm][tn], a[tm], bg[tn]);
                    mma_tf32(au[tm][tn], a[tm], bu[tn]);
                }
        }
    }
    __syncthreads();
    #pragma unroll
    for (int tm = 0; tm < 4; tm++) {
        int r0 = m0 + wm * 64 + tm * 16 + gid;
        int r1 = r0 + 8;
        #pragma unroll
        for (int tn = 0; tn < 2; tn++) {
            int c0 = n0 + wn * 16 + tn * 8 + 2 * tq;
            if (r0 < cnt) {
                float g0 = ag[tm][tn][0], u0 = au[tm][tn][0];
                float g1 = ag[tm][tn][1], u1 = au[tm][tn][1];
                g_gated[(size_t)(base + r0) * F_ + c0]     = u0 * (g0 / (1.f + __expf(-g0)));
                g_gated[(size_t)(base + r0) * F_ + c0 + 1] = u1 * (g1 / (1.f + __expf(-g1)));
            }
            if (r1 < cnt) {
                float g2 = ag[tm][tn][2], u2 = au[tm][tn][2];
                float g3 = ag[tm][tn][3], u3 = au[tm][tn][3];
                g_gated[(size_t)(base + r1) * F_ + c0]     = u2 * (g2 / (1.f + __expf(-g2)));
                g_gated[(size_t)(base + r1) * F_ + c0 + 1] = u3 * (g3 / (1.f + __expf(-g3)));
            }
        }
    }
}

__global__ void __launch_bounds__(256, 2) k_down(const float* __restrict__ down_w)
{
    extern __shared__ float dsm[];
    const int e = blockIdx.z;
    const int cnt = g_counts[e];
    if ((int)blockIdx.y * 128 >= cnt) return;
    const int base = g_offsets[e];
    gemm_tf32_body(dsm, g_gated + (size_t)base * F_, F_,
                   down_w + (size_t)e * F_ * D_, D_,
                   g_pairout + (size_t)base * D_, D_,
                   blockIdx.x * 128, F_, nullptr, cnt);
}

__global__ void k_combine(float* __restrict__ out)
{
    const int t = blockIdx.x;
    const int s0 = g_pair_slot[t * 4 + 0], s1 = g_pair_slot[t * 4 + 1];
    const int s2 = g_pair_slot[t * 4 + 2], s3 = g_pair_slot[t * 4 + 3];
    const float w0 = g_topw[t * 4 + 0], w1 = g_topw[t * 4 + 1];
    const float w2 = g_topw[t * 4 + 2], w3 = g_topw[t * 4 + 3];
    const float* p0 = g_pairout + (size_t)s0 * D_;
    const float* p1 = g_pairout + (size_t)s1 * D_;
    const float* p2 = g_pairout + (size_t)s2 * D_;
    const float* p3 = g_pairout + (size_t)s3 * D_;
    const float* hr = g_hres + (size_t)t * D_;
    float* o = out + (size_t)t * D_;
    for (int d = threadIdx.x; d < D_; d += 256)
        o[d] = hr[d] + w0 * p0[d] + w1 * p1[d] + w2 * p2[d] + w3 * p3[d];
}

// ---------------- launch ----------------
extern "C" void kernel_launch(void* const* d_in, const int* in_sizes, int n_in,
                              void* d_out, int out_size)
{
    const float* hidden = (const float*)d_in[0];
    const float* cosp   = (const float*)d_in[1];
    const float* sinp   = (const float*)d_in[2];
    const float* iln    = (const float*)d_in[4];
    const float* pln    = (const float*)d_in[5];
    const float* qw     = (const float*)d_in[6];
    const float* kw     = (const float*)d_in[7];
    const float* vw     = (const float*)d_in[8];
    const float* ow     = (const float*)d_in[9];
    const float* qnw    = (const float*)d_in[10];
    const float* knw    = (const float*)d_in[11];
    const float* gw     = (const float*)d_in[12];
    const float* guw    = (const float*)d_in[13];
    const float* dw     = (const float*)d_in[14];
    float* out = (float*)d_out;

    static bool attr_set = false;
    if (!attr_set) {
        cudaFuncSetAttribute(k_flashattn, cudaFuncAttributeMaxDynamicSharedMemorySize, FA_SMEM);
        cudaFuncSetAttribute(k_qkv,    cudaFuncAttributeMaxDynamicSharedMemorySize, GEMM_SMEM);
        cudaFuncSetAttribute(k_oproj,  cudaFuncAttributeMaxDynamicSharedMemorySize, GEMM_SMEM);
        cudaFuncSetAttribute(k_down,   cudaFuncAttributeMaxDynamicSharedMemorySize, GEMM_SMEM);
        cudaFuncSetAttribute(k_gateup, cudaFuncAttributeMaxDynamicSharedMemorySize, GU_SMEM);
        attr_set = true;
    }

    k_rmsnorm<<<T_, 256>>>(hidden, iln, 0);
    k_qkv<<<dim3(24, T_ / 128), 256, GEMM_SMEM>>>(qw, kw, vw);
    k_normrope<<<dim3(T_, NQ_), 128>>>(qnw, cosp, sinp, 0);
    k_normrope<<<dim3(T_, NKV_), 128>>>(knw, cosp, sinp, 1);
    k_flashattn<<<dim3(T_ / 64, NQ_), 256, FA_SMEM>>>();
    k_oproj<<<dim3(D_ / 128, T_ / 128), 256, GEMM_SMEM>>>(ow, hidden);
    k_rmsnorm<<<T_, 256>>>(nullptr, pln, 1);
    k_zero<<<1, 32>>>();
    k_router<<<T_, 128>>>(gw);
    k_scan<<<1, 1>>>();
    k_assign<<<(T_ * TOPK_ + 255) / 256, 256>>>();
    k_gateup<<<dim3(F_ / 64, T_ * TOPK_ / 128, E_), 256, GU_SMEM>>>(guw);
    k_down<<<dim3(D_ / 128, T_ * TOPK_ / 128, E_), 256, GEMM_SMEM>>>(dw);
    k_combine<<<T_, 256>>>(out);
}

// round 10
// speedup vs baseline: 1.0047x; 1.0047x over previous
#include <cuda_runtime.h>
#include <cuda_bf16.h>
#include <math.h>

// ---------------- problem constants ----------------
#define T_    2048
#define D_    2048
#define NQ_   16
#define NKV_  4
#define H_    128
#define E_    16
#define F_    1024
#define TOPK_ 4
#define EPS_  1e-6f
#define SCALE_ 0.088388347648318447f  // 128^-0.5

// ---------------- scratch (device globals; no allocation allowed) ----------------
__device__ float g_hnorm [(size_t)T_ * D_];
__device__ float g_q     [(size_t)T_ * NQ_ * H_];
__device__ float g_k     [(size_t)T_ * NKV_ * H_];
__device__ float g_v     [(size_t)T_ * NKV_ * H_];
__device__ float g_attnout[(size_t)T_ * NQ_ * H_];
__device__ float g_hres  [(size_t)T_ * D_];
__device__ float g_h2    [(size_t)T_ * D_];
__device__ float g_gated [(size_t)T_ * TOPK_ * F_];
__device__ float g_pairout[(size_t)T_ * TOPK_ * D_];

__device__ int   g_topidx[T_ * TOPK_];
__device__ float g_topw  [T_ * TOPK_];
__device__ int   g_counts[E_];
__device__ int   g_offsets[E_];
__device__ int   g_cursor[E_];
__device__ int   g_pair_token[T_ * TOPK_];
__device__ int   g_pair_slot [T_ * TOPK_];

// ---------------- mma / cp.async helpers ----------------
__device__ __forceinline__ void mma_tf32(float* d, const unsigned* a, const unsigned* b) {
    asm volatile(
        "mma.sync.aligned.m16n8k8.row.col.f32.tf32.tf32.f32 "
        "{%0,%1,%2,%3},{%4,%5,%6,%7},{%8,%9},{%0,%1,%2,%3};\n"
        : "+f"(d[0]), "+f"(d[1]), "+f"(d[2]), "+f"(d[3])
        : "r"(a[0]), "r"(a[1]), "r"(a[2]), "r"(a[3]), "r"(b[0]), "r"(b[1]));
}
__device__ __forceinline__ void cpa16(void* smem, const void* g) {
    unsigned s = (unsigned)__cvta_generic_to_shared(smem);
    asm volatile("cp.async.cg.shared.global [%0], [%1], 16;\n" :: "r"(s), "l"(g));
}
__device__ __forceinline__ void cpa_commit() {
    asm volatile("cp.async.commit_group;\n");
}
__device__ __forceinline__ void cpa_wait0() {
    asm volatile("cp.async.wait_group 0;\n");
}
__device__ __forceinline__ void cpa_wait1() {
    asm volatile("cp.async.wait_group 1;\n");
}

// ------- generic tf32 GEMM (NN): BK=32, 3-stage cp.async, 1 barrier/iter --------
// Tile 128x128, 256 threads (8 warps as 2x4, warp 64x32). Dynamic smem.
#define AS_LD 36
#define BS_LD 136
#define GEMM_SMEM ((3 * 128 * AS_LD + 3 * 32 * BS_LD) * 4)
__device__ __forceinline__ void gemm_tf32_body(
    float* dsm,
    const float* __restrict__ A, int lda,
    const float* __restrict__ B, int ldb,
    float* __restrict__ C, int ldc,
    int n0, int K, const float* __restrict__ resid, int mlimit)
{
    float* As = dsm;                        // [3][128][AS_LD]
    float* Bs = dsm + 3 * 128 * AS_LD;      // [3][32][BS_LD]
    const int m0 = blockIdx.y * 128;
    const int tid = threadIdx.x, lane = tid & 31, warp = tid >> 5;
    const int wm = warp >> 2, wn = warp & 3;
    const int gid = lane >> 2, tq = lane & 3;
    float acc[4][4][4] = {};

    // A: 128 rows x 32 cols/stage = 1024 float4; 4 per thread
    const int ar0 = tid >> 1;                  // 0..127
    const int ac0 = (tid & 1) * 16;            // 0 or 16 (+0,4,8,12)
    int arow = m0 + ar0; if (arow >= mlimit) arow = mlimit - 1;
    // B: 32 rows x 128 cols/stage = 1024 float4; 4 per thread
    const int br0 = tid >> 5;                  // 0..7 (+0,8,16,24)
    const int bc0 = (tid & 31) * 4;

    const int niter = K >> 5;
    auto issue = [&](int it) {
        int k0 = it << 5;
        int st = it % 3;
        float* as = As + st * 128 * AS_LD;
        float* bs = Bs + st * 32 * BS_LD;
        #pragma unroll
        for (int u = 0; u < 4; u++)
            cpa16(&as[ar0 * AS_LD + ac0 + u * 4], &A[(size_t)arow * lda + k0 + ac0 + u * 4]);
        #pragma unroll
        for (int u = 0; u < 4; u++)
            cpa16(&bs[(br0 + u * 8) * BS_LD + bc0], &B[(size_t)(k0 + br0 + u * 8) * ldb + n0 + bc0]);
        cpa_commit();
    };
    issue(0);
    if (niter > 1) issue(1);

    for (int it = 0; it < niter; it++) {
        if (it + 1 < niter) cpa_wait1(); else cpa_wait0();
        __syncthreads();
        if (it + 2 < niter) issue(it + 2);
        const float* as = As + (it % 3) * 128 * AS_LD;
        const float* bs = Bs + (it % 3) * 32 * BS_LD;
        #pragma unroll
        for (int ks = 0; ks < 32; ks += 8) {
            unsigned a[4][4], b[4][2];
            #pragma unroll
            for (int tm = 0; tm < 4; tm++) {
                int r0 = wm * 64 + tm * 16 + gid;
                a[tm][0] = __float_as_uint(as[r0 * AS_LD + ks + tq]);
                a[tm][1] = __float_as_uint(as[(r0 + 8) * AS_LD + ks + tq]);
                a[tm][2] = __float_as_uint(as[r0 * AS_LD + ks + tq + 4]);
                a[tm][3] = __float_as_uint(as[(r0 + 8) * AS_LD + ks + tq + 4]);
            }
            #pragma unroll
            for (int tn = 0; tn < 4; tn++) {
                int c = wn * 32 + tn * 8 + gid;
                b[tn][0] = __float_as_uint(bs[(ks + tq) * BS_LD + c]);
                b[tn][1] = __float_as_uint(bs[(ks + tq + 4) * BS_LD + c]);
            }
            #pragma unroll
            for (int tm = 0; tm < 4; tm++)
                #pragma unroll
                for (int tn = 0; tn < 4; tn++)
                    mma_tf32(acc[tm][tn], a[tm], b[tn]);
        }
    }
    __syncthreads();
    #pragma unroll
    for (int tm = 0; tm < 4; tm++) {
        int r0 = m0 + wm * 64 + tm * 16 + gid;
        int r1 = r0 + 8;
        #pragma unroll
        for (int tn = 0; tn < 4; tn++) {
            int c0 = n0 + wn * 32 + tn * 8 + 2 * tq;
            if (r0 < mlimit) {
                float v0 = acc[tm][tn][0], v1 = acc[tm][tn][1];
                if (resid) { v0 += resid[(size_t)r0 * ldc + c0]; v1 += resid[(size_t)r0 * ldc + c0 + 1]; }
                C[(size_t)r0 * ldc + c0] = v0; C[(size_t)r0 * ldc + c0 + 1] = v1;
            }
            if (r1 < mlimit) {
                float v2 = acc[tm][tn][2], v3 = acc[tm][tn][3];
                if (resid) { v2 += resid[(size_t)r1 * ldc + c0]; v3 += resid[(size_t)r1 * ldc + c0 + 1]; }
                C[(size_t)r1 * ldc + c0] = v2; C[(size_t)r1 * ldc + c0 + 1] = v3;
            }
        }
    }
}

// ---------------- kernels ----------------

__global__ void k_rmsnorm(const float* __restrict__ x_ext,
                          const float* __restrict__ w, int mode)
{
    const int t = blockIdx.x;
    const float* px = (mode == 0) ? (x_ext + (size_t)t * D_) : (g_hres + (size_t)t * D_);
    float* py = (mode == 0) ? (g_hnorm + (size_t)t * D_) : (g_h2 + (size_t)t * D_);
    float ss = 0.f;
    for (int d = threadIdx.x; d < D_; d += 256) { float v = px[d]; ss += v * v; }
    __shared__ float red[256];
    red[threadIdx.x] = ss; __syncthreads();
    for (int s = 128; s > 0; s >>= 1) {
        if (threadIdx.x < s) red[threadIdx.x] += red[threadIdx.x + s];
        __syncthreads();
    }
    float r = rsqrtf(red[0] / D_ + EPS_);
    for (int d = threadIdx.x; d < D_; d += 256) py[d] = px[d] * r * w[d];
}

// fused QKV projection: blockIdx.x 0..15 -> q tile, 16..19 -> k, 20..23 -> v
__global__ void __launch_bounds__(256) k_qkv(const float* __restrict__ qw,
                                             const float* __restrict__ kw,
                                             const float* __restrict__ vw)
{
    extern __shared__ float dsm[];
    const int bx = blockIdx.x;
    if (bx < 16) {
        gemm_tf32_body(dsm, g_hnorm, D_, qw, NQ_ * H_, g_q, NQ_ * H_, bx * 128, D_, nullptr, T_);
    } else if (bx < 20) {
        gemm_tf32_body(dsm, g_hnorm, D_, kw, NKV_ * H_, g_k, NKV_ * H_, (bx - 16) * 128, D_, nullptr, T_);
    } else {
        gemm_tf32_body(dsm, g_hnorm, D_, vw, NKV_ * H_, g_v, NKV_ * H_, (bx - 20) * 128, D_, nullptr, T_);
    }
}

__global__ void k_normrope(const float* __restrict__ w,
                           const float* __restrict__ cs,
                           const float* __restrict__ sn, int which)
{
    const int t = blockIdx.x, n = blockIdx.y, d = threadIdx.x; // 128 threads
    float* base = (which == 0) ? g_q : g_k;
    int nh = (which == 0) ? NQ_ : NKV_;
    float* p = base + (size_t)t * nh * H_ + (size_t)n * H_;
    float v = p[d];
    __shared__ float sh[128];
    sh[d] = v * v; __syncthreads();
    for (int s = 64; s > 0; s >>= 1) {
        if (d < s) sh[d] += sh[d + s];
        __syncthreads();
    }
    float r = rsqrtf(sh[0] / H_ + EPS_);
    __syncthreads();
    float xn = v * r * w[d];
    sh[d] = xn; __syncthreads();
    float rot = (d < 64) ? -sh[d + 64] : sh[d - 64];
    p[d] = xn * cs[(size_t)t * H_ + d] + rot * sn[(size_t)t * H_ + d];
}

// ---------------- flash attention with tf32 mma ----------------
#define FKV_LD 132
#define FPS_LD 68
#define FA_SMEM ((64 * FKV_LD + 2 * 64 * FKV_LD + 2 * 64 * FKV_LD + 64 * FPS_LD + 3 * 64) * 4)

__global__ void __launch_bounds__(256) k_flashattn()
{
    extern __shared__ float sm[];
    float* Qs    = sm;
    float* Ks    = Qs + 64 * FKV_LD;
    float* Vs    = Ks + 2 * 64 * FKV_LD;
    float* Ps    = Vs + 2 * 64 * FKV_LD;
    float* m_s   = Ps + 64 * FPS_LD;
    float* l_s   = m_s + 64;
    float* fac_s = l_s + 64;

    const int by = blockIdx.x;
    const int n  = blockIdx.y;
    const int kv = n >> 2;
    const int tid = threadIdx.x, lane = tid & 31, warp = tid >> 5;
    const int wm = warp >> 1, wn = warp & 1;
    const int gid = lane >> 2, tq = lane & 3;
    const int m0 = by * 64;

    #pragma unroll
    for (int i = 0; i < 8; i++) {
        int idx = tid + 256 * i;
        int r = idx >> 5, c4 = (idx & 31) * 4;
        cpa16(&Qs[r * FKV_LD + c4], &g_q[((size_t)(m0 + r) * NQ_ + n) * H_ + c4]);
    }
    if (tid < 64) { m_s[tid] = -1e30f; l_s[tid] = 0.f; }

    auto issue_kv = [&](int kt, int buf) {
        int s0 = kt * 64;
        float* kd = Ks + buf * 64 * FKV_LD;
        float* vd = Vs + buf * 64 * FKV_LD;
        #pragma unroll
        for (int i = 0; i < 8; i++) {
            int idx = tid + 256 * i;
            int r = idx >> 5, c4 = (idx & 31) * 4;
            cpa16(&kd[r * FKV_LD + c4], &g_k[((size_t)(s0 + r) * NKV_ + kv) * H_ + c4]);
            cpa16(&vd[r * FKV_LD + c4], &g_v[((size_t)(s0 + r) * NKV_ + kv) * H_ + c4]);
        }
        cpa_commit();
    };
    issue_kv(0, 0);

    float o[8][4] = {};

    for (int kt = 0; kt <= by; kt++) {
        cpa_wait0();
        __syncthreads();
        if (kt < by) issue_kv(kt + 1, (kt + 1) & 1);

        const float* K = Ks + (kt & 1) * 64 * FKV_LD;
        const float* V = Vs + (kt & 1) * 64 * FKV_LD;

        float s[4][4] = {};
        #pragma unroll
        for (int ks = 0; ks < H_; ks += 8) {
            unsigned a[4], b[4][2];
            int r0 = wm * 16 + gid;
            a[0] = __float_as_uint(Qs[r0 * FKV_LD + ks + tq]);
            a[1] = __float_as_uint(Qs[(r0 + 8) * FKV_LD + ks + tq]);
            a[2] = __float_as_uint(Qs[r0 * FKV_LD + ks + tq + 4]);
            a[3] = __float_as_uint(Qs[(r0 + 8) * FKV_LD + ks + tq + 4]);
            #pragma unroll
            for (int f = 0; f < 4; f++) {
                int c = wn * 32 + f * 8 + gid;
                b[f][0] = __float_as_uint(K[c * FKV_LD + ks + tq]);
                b[f][1] = __float_as_uint(K[c * FKV_LD + ks + tq + 4]);
            }
            #pragma unroll
            for (int f = 0; f < 4; f++) mma_tf32(s[f], a, b[f]);
        }
        {
            int r0 = wm * 16 + gid;
            #pragma unroll
            for (int f = 0; f < 4; f++) {
                int c = wn * 32 + f * 8 + 2 * tq;
                float v0 = s[f][0] * SCALE_, v1 = s[f][1] * SCALE_;
                float v2 = s[f][2] * SCALE_, v3 = s[f][3] * SCALE_;
                if (kt == by) {
                    if (c     > r0)     v0 = -1e30f;
                    if (c + 1 > r0)     v1 = -1e30f;
                    if (c     > r0 + 8) v2 = -1e30f;
                    if (c + 1 > r0 + 8) v3 = -1e30f;
                }
                Ps[r0 * FPS_LD + c] = v0;       Ps[r0 * FPS_LD + c + 1] = v1;
                Ps[(r0 + 8) * FPS_LD + c] = v2; Ps[(r0 + 8) * FPS_LD + c + 1] = v3;
            }
        }
        __syncthreads();

        {
            int row = tid >> 2, sub = tid & 3;
            float* pr = Ps + row * FPS_LD + sub * 16;
            float mx = -1e30f;
            #pragma unroll
            for (int i = 0; i < 16; i++) mx = fmaxf(mx, pr[i]);
            mx = fmaxf(mx, __shfl_xor_sync(0xffffffffu, mx, 1));
            mx = fmaxf(mx, __shfl_xor_sync(0xffffffffu, mx, 2));
            float mold = m_s[row];
            float lold = l_s[row];
            float mnew = fmaxf(mold, mx);
            float fac = __expf(mold - mnew);
            float sum = 0.f;
            #pragma unroll
            for (int i = 0; i < 16; i++) {
                float p = __expf(pr[i] - mnew);
                pr[i] = p; sum += p;
            }
            sum += __shfl_xor_sync(0xffffffffu, sum, 1);
            sum += __shfl_xor_sync(0xffffffffu, sum, 2);
            m_s[row] = mnew;
            l_s[row] = lold * fac + sum;
            fac_s[row] = fac;
        }
        __syncthreads();

        {
            float f0 = fac_s[wm * 16 + gid], f1 = fac_s[wm * 16 + gid + 8];
            #pragma unroll
            for (int f = 0; f < 8; f++) {
                o[f][0] *= f0; o[f][1] *= f0; o[f][2] *= f1; o[f][3] *= f1;
            }
        }

        #pragma unroll
        for (int ks = 0; ks < 64; ks += 8) {
            unsigned a[4];
            int r0 = wm * 16 + gid;
            a[0] = __float_as_uint(Ps[r0 * FPS_LD + ks + tq]);
            a[1] = __float_as_uint(Ps[(r0 + 8) * FPS_LD + ks + tq]);
            a[2] = __float_as_uint(Ps[r0 * FPS_LD + ks + tq + 4]);
            a[3] = __float_as_uint(Ps[(r0 + 8) * FPS_LD + ks + tq + 4]);
            #pragma unroll
            for (int f = 0; f < 8; f++) {
                unsigned b[2];
                int c = wn * 64 + f * 8 + gid;
                b[0] = __float_as_uint(V[(ks + tq) * FKV_LD + c]);
                b[1] = __float_as_uint(V[(ks + tq + 4) * FKV_LD + c]);
                mma_tf32(o[f], a, b);
            }
        }
    }

    {
        float inv0 = 1.f / l_s[wm * 16 + gid];
        float inv1 = 1.f / l_s[wm * 16 + gid + 8];
        int r0 = m0 + wm * 16 + gid;
        int r1 = r0 + 8;
        #pragma unroll
        for (int f = 0; f < 8; f++) {
            int c = wn * 64 + f * 8 + 2 * tq;
            float* d0 = &g_attnout[((size_t)r0 * NQ_ + n) * H_ + c];
            float* d1 = &g_attnout[((size_t)r1 * NQ_ + n) * H_ + c];
            d0[0] = o[f][0] * inv0; d0[1] = o[f][1] * inv0;
            d1[0] = o[f][2] * inv1; d1[1] = o[f][3] * inv1;
        }
    }
}

__global__ void __launch_bounds__(256) k_oproj(const float* __restrict__ W,
                                               const float* __restrict__ resid)
{
    extern __shared__ float dsm[];
    gemm_tf32_body(dsm, g_attnout, NQ_ * H_, W, D_, g_hres, D_,
                   blockIdx.x * 128, NQ_ * H_, resid, T_);
}

__global__ void k_zero()
{
    if (threadIdx.x < E_) g_counts[threadIdx.x] = 0;
}

__global__ void k_router(const float* __restrict__ gate_w)
{
    const int t = blockIdx.x, tid = threadIdx.x; // 128 threads
    const float* x = g_h2 + (size_t)t * D_;
    float acc[E_];
    #pragma unroll
    for (int e = 0; e < E_; e++) acc[e] = 0.f;
    for (int d = tid; d < D_; d += 128) {
        float xv = x[d];
        const float* gw = gate_w + (size_t)d * E_;
        #pragma unroll
        for (int e = 0; e < E_; e++) acc[e] = fmaf(xv, gw[e], acc[e]);
    }
    __shared__ float sh[128 * E_];
    #pragma unroll
    for (int e = 0; e < E_; e++) sh[tid * E_ + e] = acc[e];
    __syncthreads();
    for (int s = 64; s > 0; s >>= 1) {
        if (tid < s)
            #pragma unroll
            for (int e = 0; e < E_; e++) sh[tid * E_ + e] += sh[(tid + s) * E_ + e];
        __syncthreads();
    }
    if (tid == 0) {
        float p[E_];
        float m = -1e30f;
        for (int e = 0; e < E_; e++) m = fmaxf(m, sh[e]);
        float sum = 0.f;
        for (int e = 0; e < E_; e++) { p[e] = __expf(sh[e] - m); sum += p[e]; }
        float invs = 1.f / sum;
        for (int e = 0; e < E_; e++) p[e] *= invs;
        int idx[TOPK_]; float wv[TOPK_]; float wsum = 0.f;
        for (int k = 0; k < TOPK_; k++) {
            int best = 0; float bv = p[0];
            for (int e = 1; e < E_; e++) if (p[e] > bv) { bv = p[e]; best = e; }
            idx[k] = best; wv[k] = bv; wsum += bv; p[best] = -1.f;
        }
        float invw = 1.f / wsum;
        for (int k = 0; k < TOPK_; k++) {
            g_topidx[t * TOPK_ + k] = idx[k];
            g_topw[t * TOPK_ + k] = wv[k] * invw;
            atomicAdd(&g_counts[idx[k]], 1);
        }
    }
}

__global__ void k_scan()
{
    int off = 0;
    for (int e = 0; e < E_; e++) {
        g_offsets[e] = off;
        off += g_counts[e];
        g_cursor[e] = 0;
    }
}

__global__ void k_assign()
{
    int i = blockIdx.x * blockDim.x + threadIdx.x;
    if (i >= T_ * TOPK_) return;
    int e = g_topidx[i];
    int slot = g_offsets[e] + atomicAdd(&g_cursor[e], 1);
    g_pair_token[slot] = i >> 2;
    g_pair_slot[i] = slot;
}

// ------- MoE gate_up: BK=32, 3-stage cp.async, 1 barrier/iter, SiLU epilogue ----
#define BGU_LD 72
#define GU_SMEM ((3 * 128 * AS_LD + 2 * 3 * 32 * BGU_LD) * 4)
__global__ void __launch_bounds__(256) k_gateup(const float* __restrict__ gate_up_w)
{
    extern __shared__ float dsm[];
    float* As = dsm;                                 // [3][128][AS_LD]
    float* Bg = dsm + 3 * 128 * AS_LD;               // [3][32][BGU_LD]
    float* Bu = Bg + 3 * 32 * BGU_LD;                // [3][32][BGU_LD]
    __shared__ int rowTok[128];

    const int e = blockIdx.z;
    const int cnt = g_counts[e];
    const int m0 = blockIdx.y * 128;
    if (m0 >= cnt) return;
    const int base = g_offsets[e];
    const int n0 = blockIdx.x * 64;
    const float* B = gate_up_w + (size_t)e * D_ * (2 * F_);

    const int tid = threadIdx.x, lane = tid & 31, warp = tid >> 5;
    const int wm = warp >> 2, wn = warp & 3;
    const int gid = lane >> 2, tq = lane & 3;

    if (tid < 128) {
        int r = m0 + tid;
        rowTok[tid] = (r < cnt) ? g_pair_token[base + r] : g_pair_token[base];
    }
    __syncthreads();

    const int ar0 = tid >> 1;
    const int ac0 = (tid & 1) * 16;
    const size_t arow = (size_t)rowTok[ar0] * D_;
    const int br0 = tid >> 4;          // 0..15 (+0,16)
    const int bc0 = (tid & 15) * 4;    // 0..60

    float ag[4][2][4] = {}, au[4][2][4] = {};

    const int niter = D_ >> 5;
    auto issue = [&](int it) {
        int k0 = it << 5;
        int st = it % 3;
        float* as = As + st * 128 * AS_LD;
        float* bgp = Bg + st * 32 * BGU_LD;
        float* bup = Bu + st * 32 * BGU_LD;
        #pragma unroll
        for (int u = 0; u < 4; u++)
            cpa16(&as[ar0 * AS_LD + ac0 + u * 4], &g_h2[arow + k0 + ac0 + u * 4]);
        #pragma unroll
        for (int u = 0; u < 2; u++) {
            const float* brow = B + (size_t)(k0 + br0 + u * 16) * (2 * F_);
            cpa16(&bgp[(br0 + u * 16) * BGU_LD + bc0], &brow[n0 + bc0]);
            cpa16(&bup[(br0 + u * 16) * BGU_LD + bc0], &brow[F_ + n0 + bc0]);
        }
        cpa_commit();
    };
    issue(0);
    issue(1);

    for (int it = 0; it < niter; it++) {
        if (it + 1 < niter) cpa_wait1(); else cpa_wait0();
        __syncthreads();
        if (it + 2 < niter) issue(it + 2);
        const float* as = As + (it % 3) * 128 * AS_LD;
        const float* bgp = Bg + (it % 3) * 32 * BGU_LD;
        const float* bup = Bu + (it % 3) * 32 * BGU_LD;
        #pragma unroll
        for (int ks = 0; ks < 32; ks += 8) {
            unsigned a[4][4], bg[2][2], bu[2][2];
            #pragma unroll
            for (int tm = 0; tm < 4; tm++) {
                int r0 = wm * 64 + tm * 16 + gid;
                a[tm][0] = __float_as_uint(as[r0 * AS_LD + ks + tq]);
                a[tm][1] = __float_as_uint(as[(r0 + 8) * AS_LD + ks + tq]);
                a[tm][2] = __float_as_uint(as[r0 * AS_LD + ks + tq + 4]);
                a[tm][3] = __float_as_uint(as[(r0 + 8) * AS_LD + ks + tq + 4]);
            }
            #pragma unroll
            for (int tn = 0; tn < 2; tn++) {
                int c = wn * 16 + tn * 8 + gid;
                bg[tn][0] = __float_as_uint(bgp[(ks + tq) * BGU_LD + c]);
                bg[tn][1] = __float_as_uint(bgp[(ks + tq + 4) * BGU_LD + c]);
                bu[tn][0] = __float_as_uint(bup[(ks + tq) * BGU_LD + c]);
                bu[tn][1] = __float_as_uint(bup[(ks + tq + 4) * BGU_LD + c]);
            }
            #pragma unroll
            for (int tm = 0; tm < 4; tm++)
                #pragma unroll
                for (int tn = 0; tn < 2; tn++) {
                    mma_tf32(ag[tm][tn], a[tm], bg[tn]);
                    mma_tf32(au[tm][tn], a[tm], bu[tn]);
                }
        }
    }
    __syncthreads();
    #pragma unroll
    for (int tm = 0; tm < 4; tm++) {
        int r0 = m0 + wm * 64 + tm * 16 + gid;
        int r1 = r0 + 8;
        #pragma unroll
        for (int tn = 0; tn < 2; tn++) {
            int c0 = n0 + wn * 16 + tn * 8 + 2 * tq;
            if (r0 < cnt) {
                float g0 = ag[tm][tn][0], u0 = au[tm][tn][0];
                float g1 = ag[tm][tn][1], u1 = au[tm][tn][1];
                g_gated[(size_t)(base + r0) * F_ + c0]     = u0 * (g0 / (1.f + __expf(-g0)));
                g_gated[(size_t)(base + r0) * F_ + c0 + 1] = u1 * (g1 / (1.f + __expf(-g1)));
            }
            if (r1 < cnt) {
                float g2 = ag[tm][tn][2], u2 = au[tm][tn][2];
                float g3 = ag[tm][tn][3], u3 = au[tm][tn][3];
                g_gated[(size_t)(base + r1) * F_ + c0]     = u2 * (g2 / (1.f + __expf(-g2)));
                g_gated[(size_t)(base + r1) * F_ + c0 + 1] = u3 * (g3 / (1.f + __expf(-g3)));
            }
        }
    }
}

__global__ void __launch_bounds__(256) k_down(const float* __restrict__ down_w)
{
    extern __shared__ float dsm[];
    const int e = blockIdx.z;
    const int cnt = g_counts[e];
    if ((int)blockIdx.y * 128 >= cnt) return;
    const int base = g_offsets[e];
    gemm_tf32_body(dsm, g_gated + (size_t)base * F_, F_,
                   down_w + (size_t)e * F_ * D_, D_,
                   g_pairout + (size_t)base * D_, D_,
                   blockIdx.x * 128, F_, nullptr, cnt);
}

__global__ void k_combine(float* __restrict__ out)
{
    const int t = blockIdx.x;
    const int s0 = g_pair_slot[t * 4 + 0], s1 = g_pair_slot[t * 4 + 1];
    const int s2 = g_pair_slot[t * 4 + 2], s3 = g_pair_slot[t * 4 + 3];
    const float w0 = g_topw[t * 4 + 0], w1 = g_topw[t * 4 + 1];
    const float w2 = g_topw[t * 4 + 2], w3 = g_topw[t * 4 + 3];
    const float* p0 = g_pairout + (size_t)s0 * D_;
    const float* p1 = g_pairout + (size_t)s1 * D_;
    const float* p2 = g_pairout + (size_t)s2 * D_;
    const float* p3 = g_pairout + (size_t)s3 * D_;
    const float* hr = g_hres + (size_t)t * D_;
    float* o = out + (size_t)t * D_;
    for (int d = threadIdx.x; d < D_; d += 256)
        o[d] = hr[d] + w0 * p0[d] + w1 * p1[d] + w2 * p2[d] + w3 * p3[d];
}

// ---------------- launch ----------------
extern "C" void kernel_launch(void* const* d_in, const int* in_sizes, int n_in,
                              void* d_out, int out_size)
{
    const float* hidden = (const float*)d_in[0];
    const float* cosp   = (const float*)d_in[1];
    const float* sinp   = (const float*)d_in[2];
    const float* iln    = (const float*)d_in[4];
    const float* pln    = (const float*)d_in[5];
    const float* qw     = (const float*)d_in[6];
    const float* kw     = (const float*)d_in[7];
    const float* vw     = (const float*)d_in[8];
    const float* ow     = (const float*)d_in[9];
    const float* qnw    = (const float*)d_in[10];
    const float* knw    = (const float*)d_in[11];
    const float* gw     = (const float*)d_in[12];
    const float* guw    = (const float*)d_in[13];
    const float* dw     = (const float*)d_in[14];
    float* out = (float*)d_out;

    static bool attr_set = false;
    if (!attr_set) {
        cudaFuncSetAttribute(k_flashattn, cudaFuncAttributeMaxDynamicSharedMemorySize, FA_SMEM);
        cudaFuncSetAttribute(k_qkv,    cudaFuncAttributeMaxDynamicSharedMemorySize, GEMM_SMEM);
        cudaFuncSetAttribute(k_oproj,  cudaFuncAttributeMaxDynamicSharedMemorySize, GEMM_SMEM);
        cudaFuncSetAttribute(k_down,   cudaFuncAttributeMaxDynamicSharedMemorySize, GEMM_SMEM);
        cudaFuncSetAttribute(k_gateup, cudaFuncAttributeMaxDynamicSharedMemorySize, GU_SMEM);
        attr_set = true;
    }

    k_rmsnorm<<<T_, 256>>>(hidden, iln, 0);
    k_qkv<<<dim3(24, T_ / 128), 256, GEMM_SMEM>>>(qw, kw, vw);
    k_normrope<<<dim3(T_, NQ_), 128>>>(qnw, cosp, sinp, 0);
    k_normrope<<<dim3(T_, NKV_), 128>>>(knw, cosp, sinp, 1);
    k_flashattn<<<dim3(T_ / 64, NQ_), 256, FA_SMEM>>>();
    k_oproj<<<dim3(D_ / 128, T_ / 128), 256, GEMM_SMEM>>>(ow, hidden);
    k_rmsnorm<<<T_, 256>>>(nullptr, pln, 1);
    k_zero<<<1, 32>>>();
    k_router<<<T_, 128>>>(gw);
    k_scan<<<1, 1>>>();
    k_assign<<<(T_ * TOPK_ + 255) / 256, 256>>>();
    k_gateup<<<dim3(F_ / 64, T_ * TOPK_ / 128, E_), 256, GU_SMEM>>>(guw);
    k_down<<<dim3(D_ / 128, T_ * TOPK_ / 128, E_), 256, GEMM_SMEM>>>(dw);
    k_combine<<<T_, 256>>>(out);
}

// round 11
// speedup vs baseline: 1.0157x; 1.0110x over previous
#include <cuda_runtime.h>
#include <cuda_bf16.h>
#include <math.h>

// ---------------- problem constants ----------------
#define T_    2048
#define D_    2048
#define NQ_   16
#define NKV_  4
#define H_    128
#define E_    16
#define F_    1024
#define TOPK_ 4
#define EPS_  1e-6f
#define SCALE_ 0.088388347648318447f  // 128^-0.5

// ---------------- scratch (device globals; no allocation allowed) ----------------
__device__ float g_hnorm [(size_t)T_ * D_];
__device__ float g_q     [(size_t)T_ * NQ_ * H_];
__device__ float g_k     [(size_t)T_ * NKV_ * H_];
__device__ float g_v     [(size_t)T_ * NKV_ * H_];
__device__ float g_attnout[(size_t)T_ * NQ_ * H_];
__device__ float g_hres  [(size_t)T_ * D_];
__device__ float g_h2    [(size_t)T_ * D_];
__device__ float g_gated [(size_t)T_ * TOPK_ * F_];
__device__ float g_pairout[(size_t)T_ * TOPK_ * D_];

__device__ int   g_topidx[T_ * TOPK_];
__device__ float g_topw  [T_ * TOPK_];
__device__ int   g_counts[E_];
__device__ int   g_offsets[E_];
__device__ int   g_cursor[E_];
__device__ int   g_pair_token[T_ * TOPK_];
__device__ int   g_pair_slot [T_ * TOPK_];

// ---------------- mma / cp.async helpers ----------------
__device__ __forceinline__ void mma_tf32(float* d, const unsigned* a, const unsigned* b) {
    asm volatile(
        "mma.sync.aligned.m16n8k8.row.col.f32.tf32.tf32.f32 "
        "{%0,%1,%2,%3},{%4,%5,%6,%7},{%8,%9},{%0,%1,%2,%3};\n"
        : "+f"(d[0]), "+f"(d[1]), "+f"(d[2]), "+f"(d[3])
        : "r"(a[0]), "r"(a[1]), "r"(a[2]), "r"(a[3]), "r"(b[0]), "r"(b[1]));
}
__device__ __forceinline__ void cpa16(void* smem, const void* g) {
    unsigned s = (unsigned)__cvta_generic_to_shared(smem);
    asm volatile("cp.async.cg.shared.global [%0], [%1], 16;\n" :: "r"(s), "l"(g));
}
__device__ __forceinline__ void cpa_commit() {
    asm volatile("cp.async.commit_group;\n");
}
__device__ __forceinline__ void cpa_wait0() {
    asm volatile("cp.async.wait_group 0;\n");
}
__device__ __forceinline__ void cpa_wait1() {
    asm volatile("cp.async.wait_group 1;\n");
}

// ------- generic tf32 GEMM (NN): BK=16, 3-stage cp.async, ONE barrier/iter ------
// Tile 128x128, 256 threads (8 warps as 2x4). ~57KB dynamic smem (2+ CTA/SM).
#define AS_LD 20
#define BS_LD 136
#define GEMM_SMEM ((3 * 128 * AS_LD + 3 * 16 * BS_LD) * 4)
__device__ __forceinline__ void gemm_tf32_body(
    float* dsm,
    const float* __restrict__ A, int lda,
    const float* __restrict__ B, int ldb,
    float* __restrict__ C, int ldc,
    int n0, int K, const float* __restrict__ resid, int mlimit)
{
    float* As = dsm;                        // [3][128][AS_LD]
    float* Bs = dsm + 3 * 128 * AS_LD;      // [3][16][BS_LD]
    const int m0 = blockIdx.y * 128;
    const int tid = threadIdx.x, lane = tid & 31, warp = tid >> 5;
    const int wm = warp >> 2, wn = warp & 3;
    const int gid = lane >> 2, tq = lane & 3;
    float acc[4][4][4] = {};

    const int ar0 = tid >> 1;                 // 0..127
    const int ac0 = (tid & 1) * 8;            // 0 or 8
    int arow = m0 + ar0; if (arow >= mlimit) arow = mlimit - 1;
    const int br0 = tid >> 5;                 // 0..7 (+8)
    const int bc0 = (tid & 31) * 4;

    const int niter = K >> 4;
    auto issue = [&](int it) {
        int k0 = it << 4;
        int st = it % 3;
        float* as = As + st * 128 * AS_LD;
        float* bs = Bs + st * 16 * BS_LD;
        cpa16(&as[ar0 * AS_LD + ac0],     &A[(size_t)arow * lda + k0 + ac0]);
        cpa16(&as[ar0 * AS_LD + ac0 + 4], &A[(size_t)arow * lda + k0 + ac0 + 4]);
        cpa16(&bs[br0 * BS_LD + bc0],       &B[(size_t)(k0 + br0) * ldb + n0 + bc0]);
        cpa16(&bs[(br0 + 8) * BS_LD + bc0], &B[(size_t)(k0 + br0 + 8) * ldb + n0 + bc0]);
        cpa_commit();
    };
    issue(0);
    if (niter > 1) issue(1);

    for (int it = 0; it < niter; it++) {
        if (it + 1 < niter) cpa_wait1(); else cpa_wait0();
        __syncthreads();   // orders compute(it-1) before issue(it+2) overwrite; no 2nd barrier needed
        if (it + 2 < niter) issue(it + 2);
        const float* as = As + (it % 3) * 128 * AS_LD;
        const float* bs = Bs + (it % 3) * 16 * BS_LD;
        #pragma unroll
        for (int ks = 0; ks < 16; ks += 8) {
            unsigned a[4][4], b[4][2];
            #pragma unroll
            for (int tm = 0; tm < 4; tm++) {
                int r0 = wm * 64 + tm * 16 + gid;
                a[tm][0] = __float_as_uint(as[r0 * AS_LD + ks + tq]);
                a[tm][1] = __float_as_uint(as[(r0 + 8) * AS_LD + ks + tq]);
                a[tm][2] = __float_as_uint(as[r0 * AS_LD + ks + tq + 4]);
                a[tm][3] = __float_as_uint(as[(r0 + 8) * AS_LD + ks + tq + 4]);
            }
            #pragma unroll
            for (int tn = 0; tn < 4; tn++) {
                int c = wn * 32 + tn * 8 + gid;
                b[tn][0] = __float_as_uint(bs[(ks + tq) * BS_LD + c]);
                b[tn][1] = __float_as_uint(bs[(ks + tq + 4) * BS_LD + c]);
            }
            #pragma unroll
            for (int tm = 0; tm < 4; tm++)
                #pragma unroll
                for (int tn = 0; tn < 4; tn++)
                    mma_tf32(acc[tm][tn], a[tm], b[tn]);
        }
    }
    #pragma unroll
    for (int tm = 0; tm < 4; tm++) {
        int r0 = m0 + wm * 64 + tm * 16 + gid;
        int r1 = r0 + 8;
        #pragma unroll
        for (int tn = 0; tn < 4; tn++) {
            int c0 = n0 + wn * 32 + tn * 8 + 2 * tq;
            if (r0 < mlimit) {
                float v0 = acc[tm][tn][0], v1 = acc[tm][tn][1];
                if (resid) { v0 += resid[(size_t)r0 * ldc + c0]; v1 += resid[(size_t)r0 * ldc + c0 + 1]; }
                C[(size_t)r0 * ldc + c0] = v0; C[(size_t)r0 * ldc + c0 + 1] = v1;
            }
            if (r1 < mlimit) {
                float v2 = acc[tm][tn][2], v3 = acc[tm][tn][3];
                if (resid) { v2 += resid[(size_t)r1 * ldc + c0]; v3 += resid[(size_t)r1 * ldc + c0 + 1]; }
                C[(size_t)r1 * ldc + c0] = v2; C[(size_t)r1 * ldc + c0 + 1] = v3;
            }
        }
    }
}

// ---------------- kernels ----------------

__global__ void k_rmsnorm(const float* __restrict__ x_ext,
                          const float* __restrict__ w)
{
    const int t = blockIdx.x;
    const float* px = x_ext + (size_t)t * D_;
    float* py = g_hnorm + (size_t)t * D_;
    float ss = 0.f;
    for (int d = threadIdx.x; d < D_; d += 256) { float v = px[d]; ss += v * v; }
    __shared__ float red[256];
    red[threadIdx.x] = ss; __syncthreads();
    for (int s = 128; s > 0; s >>= 1) {
        if (threadIdx.x < s) red[threadIdx.x] += red[threadIdx.x + s];
        __syncthreads();
    }
    float r = rsqrtf(red[0] / D_ + EPS_);
    for (int d = threadIdx.x; d < D_; d += 256) py[d] = px[d] * r * w[d];
}

// fused QKV projection: blockIdx.x 0..15 -> q tile, 16..19 -> k, 20..23 -> v
__global__ void __launch_bounds__(256) k_qkv(const float* __restrict__ qw,
                                             const float* __restrict__ kw,
                                             const float* __restrict__ vw)
{
    extern __shared__ float dsm[];
    const int bx = blockIdx.x;
    if (bx < 16) {
        gemm_tf32_body(dsm, g_hnorm, D_, qw, NQ_ * H_, g_q, NQ_ * H_, bx * 128, D_, nullptr, T_);
    } else if (bx < 20) {
        gemm_tf32_body(dsm, g_hnorm, D_, kw, NKV_ * H_, g_k, NKV_ * H_, (bx - 16) * 128, D_, nullptr, T_);
    } else {
        gemm_tf32_body(dsm, g_hnorm, D_, vw, NKV_ * H_, g_v, NKV_ * H_, (bx - 20) * 128, D_, nullptr, T_);
    }
}

// merged q+k norm-rope: blockIdx.y 0..15 = q head, 16..19 = k head
__global__ void k_normrope(const float* __restrict__ qnw,
                           const float* __restrict__ knw,
                           const float* __restrict__ cs,
                           const float* __restrict__ sn)
{
    const int t = blockIdx.x, h = blockIdx.y, d = threadIdx.x; // 128 threads
    const bool isq = (h < NQ_);
    float* p = isq ? (g_q + ((size_t)t * NQ_ + h) * H_)
                   : (g_k + ((size_t)t * NKV_ + (h - NQ_)) * H_);
    const float* w = isq ? qnw : knw;
    float v = p[d];
    __shared__ float sh[128];
    sh[d] = v * v; __syncthreads();
    for (int s = 64; s > 0; s >>= 1) {
        if (d < s) sh[d] += sh[d + s];
        __syncthreads();
    }
    float r = rsqrtf(sh[0] / H_ + EPS_);
    __syncthreads();
    float xn = v * r * w[d];
    sh[d] = xn; __syncthreads();
    float rot = (d < 64) ? -sh[d + 64] : sh[d - 64];
    p[d] = xn * cs[(size_t)t * H_ + d] + rot * sn[(size_t)t * H_ + d];
}

// ---------------- flash attention with tf32 mma ----------------
#define FKV_LD 132
#define FPS_LD 68
#define FA_SMEM ((64 * FKV_LD + 2 * 64 * FKV_LD + 2 * 64 * FKV_LD + 64 * FPS_LD + 3 * 64) * 4)

__global__ void __launch_bounds__(256) k_flashattn()
{
    extern __shared__ float sm[];
    float* Qs    = sm;
    float* Ks    = Qs + 64 * FKV_LD;
    float* Vs    = Ks + 2 * 64 * FKV_LD;
    float* Ps    = Vs + 2 * 64 * FKV_LD;
    float* m_s   = Ps + 64 * FPS_LD;
    float* l_s   = m_s + 64;
    float* fac_s = l_s + 64;

    const int by = blockIdx.x;
    const int n  = blockIdx.y;
    const int kv = n >> 2;
    const int tid = threadIdx.x, lane = tid & 31, warp = tid >> 5;
    const int wm = warp >> 1, wn = warp & 1;
    const int gid = lane >> 2, tq = lane & 3;
    const int m0 = by * 64;

    #pragma unroll
    for (int i = 0; i < 8; i++) {
        int idx = tid + 256 * i;
        int r = idx >> 5, c4 = (idx & 31) * 4;
        cpa16(&Qs[r * FKV_LD + c4], &g_q[((size_t)(m0 + r) * NQ_ + n) * H_ + c4]);
    }
    if (tid < 64) { m_s[tid] = -1e30f; l_s[tid] = 0.f; }

    auto issue_kv = [&](int kt, int buf) {
        int s0 = kt * 64;
        float* kd = Ks + buf * 64 * FKV_LD;
        float* vd = Vs + buf * 64 * FKV_LD;
        #pragma unroll
        for (int i = 0; i < 8; i++) {
            int idx = tid + 256 * i;
            int r = idx >> 5, c4 = (idx & 31) * 4;
            cpa16(&kd[r * FKV_LD + c4], &g_k[((size_t)(s0 + r) * NKV_ + kv) * H_ + c4]);
            cpa16(&vd[r * FKV_LD + c4], &g_v[((size_t)(s0 + r) * NKV_ + kv) * H_ + c4]);
        }
        cpa_commit();
    };
    issue_kv(0, 0);

    float o[8][4] = {};

    for (int kt = 0; kt <= by; kt++) {
        cpa_wait0();
        __syncthreads();
        if (kt < by) issue_kv(kt + 1, (kt + 1) & 1);

        const float* K = Ks + (kt & 1) * 64 * FKV_LD;
        const float* V = Vs + (kt & 1) * 64 * FKV_LD;

        float s[4][4] = {};
        #pragma unroll
        for (int ks = 0; ks < H_; ks += 8) {
            unsigned a[4], b[4][2];
            int r0 = wm * 16 + gid;
            a[0] = __float_as_uint(Qs[r0 * FKV_LD + ks + tq]);
            a[1] = __float_as_uint(Qs[(r0 + 8) * FKV_LD + ks + tq]);
            a[2] = __float_as_uint(Qs[r0 * FKV_LD + ks + tq + 4]);
            a[3] = __float_as_uint(Qs[(r0 + 8) * FKV_LD + ks + tq + 4]);
            #pragma unroll
            for (int f = 0; f < 4; f++) {
                int c = wn * 32 + f * 8 + gid;
                b[f][0] = __float_as_uint(K[c * FKV_LD + ks + tq]);
                b[f][1] = __float_as_uint(K[c * FKV_LD + ks + tq + 4]);
            }
            #pragma unroll
            for (int f = 0; f < 4; f++) mma_tf32(s[f], a, b[f]);
        }
        {
            int r0 = wm * 16 + gid;
            #pragma unroll
            for (int f = 0; f < 4; f++) {
                int c = wn * 32 + f * 8 + 2 * tq;
                float v0 = s[f][0] * SCALE_, v1 = s[f][1] * SCALE_;
                float v2 = s[f][2] * SCALE_, v3 = s[f][3] * SCALE_;
                if (kt == by) {
                    if (c     > r0)     v0 = -1e30f;
                    if (c + 1 > r0)     v1 = -1e30f;
                    if (c     > r0 + 8) v2 = -1e30f;
                    if (c + 1 > r0 + 8) v3 = -1e30f;
                }
                Ps[r0 * FPS_LD + c] = v0;       Ps[r0 * FPS_LD + c + 1] = v1;
                Ps[(r0 + 8) * FPS_LD + c] = v2; Ps[(r0 + 8) * FPS_LD + c + 1] = v3;
            }
        }
        __syncthreads();

        {
            int row = tid >> 2, sub = tid & 3;
            float* pr = Ps + row * FPS_LD + sub * 16;
            float mx = -1e30f;
            #pragma unroll
            for (int i = 0; i < 16; i++) mx = fmaxf(mx, pr[i]);
            mx = fmaxf(mx, __shfl_xor_sync(0xffffffffu, mx, 1));
            mx = fmaxf(mx, __shfl_xor_sync(0xffffffffu, mx, 2));
            float mold = m_s[row];
            float lold = l_s[row];
            float mnew = fmaxf(mold, mx);
            float fac = __expf(mold - mnew);
            float sum = 0.f;
            #pragma unroll
            for (int i = 0; i < 16; i++) {
                float p = __expf(pr[i] - mnew);
                pr[i] = p; sum += p;
            }
            sum += __shfl_xor_sync(0xffffffffu, sum, 1);
            sum += __shfl_xor_sync(0xffffffffu, sum, 2);
            m_s[row] = mnew;
            l_s[row] = lold * fac + sum;
            fac_s[row] = fac;
        }
        __syncthreads();

        {
            float f0 = fac_s[wm * 16 + gid], f1 = fac_s[wm * 16 + gid + 8];
            #pragma unroll
            for (int f = 0; f < 8; f++) {
                o[f][0] *= f0; o[f][1] *= f0; o[f][2] *= f1; o[f][3] *= f1;
            }
        }

        #pragma unroll
        for (int ks = 0; ks < 64; ks += 8) {
            unsigned a[4];
            int r0 = wm * 16 + gid;
            a[0] = __float_as_uint(Ps[r0 * FPS_LD + ks + tq]);
            a[1] = __float_as_uint(Ps[(r0 + 8) * FPS_LD + ks + tq]);
            a[2] = __float_as_uint(Ps[r0 * FPS_LD + ks + tq + 4]);
            a[3] = __float_as_uint(Ps[(r0 + 8) * FPS_LD + ks + tq + 4]);
            #pragma unroll
            for (int f = 0; f < 8; f++) {
                unsigned b[2];
                int c = wn * 64 + f * 8 + gid;
                b[0] = __float_as_uint(V[(ks + tq) * FKV_LD + c]);
                b[1] = __float_as_uint(V[(ks + tq + 4) * FKV_LD + c]);
                mma_tf32(o[f], a, b);
            }
        }
    }

    {
        float inv0 = 1.f / l_s[wm * 16 + gid];
        float inv1 = 1.f / l_s[wm * 16 + gid + 8];
        int r0 = m0 + wm * 16 + gid;
        int r1 = r0 + 8;
        #pragma unroll
        for (int f = 0; f < 8; f++) {
            int c = wn * 64 + f * 8 + 2 * tq;
            float* d0 = &g_attnout[((size_t)r0 * NQ_ + n) * H_ + c];
            float* d1 = &g_attnout[((size_t)r1 * NQ_ + n) * H_ + c];
            d0[0] = o[f][0] * inv0; d0[1] = o[f][1] * inv0;
            d1[0] = o[f][2] * inv1; d1[1] = o[f][3] * inv1;
        }
    }
}

__global__ void __launch_bounds__(256) k_oproj(const float* __restrict__ W,
                                               const float* __restrict__ resid)
{
    extern __shared__ float dsm[];
    gemm_tf32_body(dsm, g_attnout, NQ_ * H_, W, D_, g_hres, D_,
                   blockIdx.x * 128, NQ_ * H_, resid, T_);
}

__global__ void k_zero()
{
    if (threadIdx.x < E_) g_counts[threadIdx.x] = 0;
}

// fused post-attn RMSNorm + router (per token): g_hres -> g_h2, topk, counts
__global__ void k_rms_router(const float* __restrict__ pln,
                             const float* __restrict__ gate_w)
{
    const int t = blockIdx.x, tid = threadIdx.x;   // 256 threads
    const float* px = g_hres + (size_t)t * D_;
    float* py = g_h2 + (size_t)t * D_;
    float xv[8];
    float ss = 0.f;
    #pragma unroll
    for (int i = 0; i < 8; i++) {
        float v = px[tid + 256 * i];
        xv[i] = v; ss += v * v;
    }
    __shared__ float red[256];
    red[tid] = ss; __syncthreads();
    for (int s = 128; s > 0; s >>= 1) {
        if (tid < s) red[tid] += red[tid + s];
        __syncthreads();
    }
    const float r = rsqrtf(red[0] / D_ + EPS_);

    float acc[E_];
    #pragma unroll
    for (int e = 0; e < E_; e++) acc[e] = 0.f;
    #pragma unroll
    for (int i = 0; i < 8; i++) {
        int d = tid + 256 * i;
        float y = xv[i] * r * pln[d];
        py[d] = y;
        const float* gw = gate_w + (size_t)d * E_;
        #pragma unroll
        for (int e = 0; e < E_; e++) acc[e] = fmaf(y, gw[e], acc[e]);
    }
    __shared__ float sh[256 * E_];
    #pragma unroll
    for (int e = 0; e < E_; e++) sh[tid * E_ + e] = acc[e];
    __syncthreads();
    for (int s = 128; s > 0; s >>= 1) {
        if (tid < s)
            #pragma unroll
            for (int e = 0; e < E_; e++) sh[tid * E_ + e] += sh[(tid + s) * E_ + e];
        __syncthreads();
    }
    if (tid == 0) {
        float p[E_];
        float m = -1e30f;
        for (int e = 0; e < E_; e++) m = fmaxf(m, sh[e]);
        float sum = 0.f;
        for (int e = 0; e < E_; e++) { p[e] = __expf(sh[e] - m); sum += p[e]; }
        float invs = 1.f / sum;
        for (int e = 0; e < E_; e++) p[e] *= invs;
        int idx[TOPK_]; float wv[TOPK_]; float wsum = 0.f;
        for (int k = 0; k < TOPK_; k++) {
            int best = 0; float bv = p[0];
            for (int e = 1; e < E_; e++) if (p[e] > bv) { bv = p[e]; best = e; }
            idx[k] = best; wv[k] = bv; wsum += bv; p[best] = -1.f;
        }
        float invw = 1.f / wsum;
        for (int k = 0; k < TOPK_; k++) {
            g_topidx[t * TOPK_ + k] = idx[k];
            g_topw[t * TOPK_ + k] = wv[k] * invw;
            atomicAdd(&g_counts[idx[k]], 1);
        }
    }
}

__global__ void k_scan()
{
    int off = 0;
    for (int e = 0; e < E_; e++) {
        g_offsets[e] = off;
        off += g_counts[e];
        g_cursor[e] = 0;
    }
}

__global__ void k_assign()
{
    int i = blockIdx.x * blockDim.x + threadIdx.x;
    if (i >= T_ * TOPK_) return;
    int e = g_topidx[i];
    int slot = g_offsets[e] + atomicAdd(&g_cursor[e], 1);
    g_pair_token[slot] = i >> 2;
    g_pair_slot[i] = slot;
}

// ------- MoE gate_up: BK=16, 3-stage cp.async, ONE barrier/iter, SiLU epilogue --
#define BGU_LD 72
#define GU_SMEM ((3 * 128 * AS_LD + 2 * 3 * 16 * BGU_LD) * 4)
__global__ void __launch_bounds__(256) k_gateup(const float* __restrict__ gate_up_w)
{
    extern __shared__ float dsm[];
    float* As = dsm;                                 // [3][128][AS_LD]
    float* Bg = dsm + 3 * 128 * AS_LD;               // [3][16][BGU_LD]
    float* Bu = Bg + 3 * 16 * BGU_LD;                // [3][16][BGU_LD]
    __shared__ int rowTok[128];

    const int e = blockIdx.z;
    const int cnt = g_counts[e];
    const int m0 = blockIdx.y * 128;
    if (m0 >= cnt) return;
    const int base = g_offsets[e];
    const int n0 = blockIdx.x * 64;
    const float* B = gate_up_w + (size_t)e * D_ * (2 * F_);

    const int tid = threadIdx.x, lane = tid & 31, warp = tid >> 5;
    const int wm = warp >> 2, wn = warp & 3;
    const int gid = lane >> 2, tq = lane & 3;

    if (tid < 128) {
        int r = m0 + tid;
        rowTok[tid] = (r < cnt) ? g_pair_token[base + r] : g_pair_token[base];
    }
    __syncthreads();

    const int ar0 = tid >> 1;
    const int ac0 = (tid & 1) * 8;
    const size_t arow = (size_t)rowTok[ar0] * D_;
    const int br0 = tid >> 4;          // 0..15
    const int bc0 = (tid & 15) * 4;    // 0..60

    float ag[4][2][4] = {}, au[4][2][4] = {};

    const int niter = D_ >> 4;
    auto issue = [&](int it) {
        int k0 = it << 4;
        int st = it % 3;
        float* as = As + st * 128 * AS_LD;
        float* bgp = Bg + st * 16 * BGU_LD;
        float* bup = Bu + st * 16 * BGU_LD;
        cpa16(&as[ar0 * AS_LD + ac0],     &g_h2[arow + k0 + ac0]);
        cpa16(&as[ar0 * AS_LD + ac0 + 4], &g_h2[arow + k0 + ac0 + 4]);
        const float* brow = B + (size_t)(k0 + br0) * (2 * F_);
        cpa16(&bgp[br0 * BGU_LD + bc0], &brow[n0 + bc0]);
        cpa16(&bup[br0 * BGU_LD + bc0], &brow[F_ + n0 + bc0]);
        cpa_commit();
    };
    issue(0);
    issue(1);

    for (int it = 0; it < niter; it++) {
        if (it + 1 < niter) cpa_wait1(); else cpa_wait0();
        __syncthreads();
        if (it + 2 < niter) issue(it + 2);
        const float* as = As + (it % 3) * 128 * AS_LD;
        const float* bgp = Bg + (it % 3) * 16 * BGU_LD;
        const float* bup = Bu + (it % 3) * 16 * BGU_LD;
        #pragma unroll
        for (int ks = 0; ks < 16; ks += 8) {
            unsigned a[4][4], bg[2][2], bu[2][2];
            #pragma unroll
            for (int tm = 0; tm < 4; tm++) {
                int r0 = wm * 64 + tm * 16 + gid;
                a[tm][0] = __float_as_uint(as[r0 * AS_LD + ks + tq]);
                a[tm][1] = __float_as_uint(as[(r0 + 8) * AS_LD + ks + tq]);
                a[tm][2] = __float_as_uint(as[r0 * AS_LD + ks + tq + 4]);
                a[tm][3] = __float_as_uint(as[(r0 + 8) * AS_LD + ks + tq + 4]);
            }
            #pragma unroll
            for (int tn = 0; tn < 2; tn++) {
                int c = wn * 16 + tn * 8 + gid;
                bg[tn][0] = __float_as_uint(bgp[(ks + tq) * BGU_LD + c]);
                bg[tn][1] = __float_as_uint(bgp[(ks + tq + 4) * BGU_LD + c]);
                bu[tn][0] = __float_as_uint(bup[(ks + tq) * BGU_LD + c]);
                bu[tn][1] = __float_as_uint(bup[(ks + tq + 4) * BGU_LD + c]);
            }
            #pragma unroll
            for (int tm = 0; tm < 4; tm++)
                #pragma unroll
                for (int tn = 0; tn < 2; tn++) {
                    mma_tf32(ag[tm][tn], a[tm], bg[tn]);
                    mma_tf32(au[tm][tn], a[tm], bu[tn]);
                }
        }
    }
    #pragma unroll
    for (int tm = 0; tm < 4; tm++) {
        int r0 = m0 + wm * 64 + tm * 16 + gid;
        int r1 = r0 + 8;
        #pragma unroll
        for (int tn = 0; tn < 2; tn++) {
            int c0 = n0 + wn * 16 + tn * 8 + 2 * tq;
            if (r0 < cnt) {
                float g0 = ag[tm][tn][0], u0 = au[tm][tn][0];
                float g1 = ag[tm][tn][1], u1 = au[tm][tn][1];
                g_gated[(size_t)(base + r0) * F_ + c0]     = u0 * (g0 / (1.f + __expf(-g0)));
                g_gated[(size_t)(base + r0) * F_ + c0 + 1] = u1 * (g1 / (1.f + __expf(-g1)));
            }
            if (r1 < cnt) {
                float g2 = ag[tm][tn][2], u2 = au[tm][tn][2];
                float g3 = ag[tm][tn][3], u3 = au[tm][tn][3];
                g_gated[(size_t)(base + r1) * F_ + c0]     = u2 * (g2 / (1.f + __expf(-g2)));
                g_gated[(size_t)(base + r1) * F_ + c0 + 1] = u3 * (g3 / (1.f + __expf(-g3)));
            }
        }
    }
}

__global__ void __launch_bounds__(256) k_down(const float* __restrict__ down_w)
{
    extern __shared__ float dsm[];
    const int e = blockIdx.z;
    const int cnt = g_counts[e];
    if ((int)blockIdx.y * 128 >= cnt) return;
    const int base = g_offsets[e];
    gemm_tf32_body(dsm, g_gated + (size_t)base * F_, F_,
                   down_w + (size_t)e * F_ * D_, D_,
                   g_pairout + (size_t)base * D_, D_,
                   blockIdx.x * 128, F_, nullptr, cnt);
}

__global__ void k_combine(float* __restrict__ out)
{
    const int t = blockIdx.x;
    const int s0 = g_pair_slot[t * 4 + 0], s1 = g_pair_slot[t * 4 + 1];
    const int s2 = g_pair_slot[t * 4 + 2], s3 = g_pair_slot[t * 4 + 3];
    const float w0 = g_topw[t * 4 + 0], w1 = g_topw[t * 4 + 1];
    const float w2 = g_topw[t * 4 + 2], w3 = g_topw[t * 4 + 3];
    const float* p0 = g_pairout + (size_t)s0 * D_;
    const float* p1 = g_pairout + (size_t)s1 * D_;
    const float* p2 = g_pairout + (size_t)s2 * D_;
    const float* p3 = g_pairout + (size_t)s3 * D_;
    const float* hr = g_hres + (size_t)t * D_;
    float* o = out + (size_t)t * D_;
    for (int d = threadIdx.x; d < D_; d += 256)
        o[d] = hr[d] + w0 * p0[d] + w1 * p1[d] + w2 * p2[d] + w3 * p3[d];
}

// ---------------- launch ----------------
extern "C" void kernel_launch(void* const* d_in, const int* in_sizes, int n_in,
                              void* d_out, int out_size)
{
    const float* hidden = (const float*)d_in[0];
    const float* cosp   = (const float*)d_in[1];
    const float* sinp   = (const float*)d_in[2];
    const float* iln    = (const float*)d_in[4];
    const float* pln    = (const float*)d_in[5];
    const float* qw     = (const float*)d_in[6];
    const float* kw     = (const float*)d_in[7];
    const float* vw     = (const float*)d_in[8];
    const float* ow     = (const float*)d_in[9];
    const float* qnw    = (const float*)d_in[10];
    const float* knw    = (const float*)d_in[11];
    const float* gw     = (const float*)d_in[12];
    const float* guw    = (const float*)d_in[13];
    const float* dw     = (const float*)d_in[14];
    float* out = (float*)d_out;

    static bool attr_set = false;
    if (!attr_set) {
        cudaFuncSetAttribute(k_flashattn, cudaFuncAttributeMaxDynamicSharedMemorySize, FA_SMEM);
        cudaFuncSetAttribute(k_qkv,    cudaFuncAttributeMaxDynamicSharedMemorySize, GEMM_SMEM);
        cudaFuncSetAttribute(k_oproj,  cudaFuncAttributeMaxDynamicSharedMemorySize, GEMM_SMEM);
        cudaFuncSetAttribute(k_down,   cudaFuncAttributeMaxDynamicSharedMemorySize, GEMM_SMEM);
        cudaFuncSetAttribute(k_gateup, cudaFuncAttributeMaxDynamicSharedMemorySize, GU_SMEM);
        attr_set = true;
    }

    k_rmsnorm<<<T_, 256>>>(hidden, iln);
    k_qkv<<<dim3(24, T_ / 128), 256, GEMM_SMEM>>>(qw, kw, vw);
    k_normrope<<<dim3(T_, NQ_ + NKV_), 128>>>(qnw, knw, cosp, sinp);
    k_flashattn<<<dim3(T_ / 64, NQ_), 256, FA_SMEM>>>();
    k_oproj<<<dim3(D_ / 128, T_ / 128), 256, GEMM_SMEM>>>(ow, hidden);
    k_zero<<<1, 32>>>();
    k_rms_router<<<T_, 256>>>(pln, gw);
    k_scan<<<1, 1>>>();
    k_assign<<<(T_ * TOPK_ + 255) / 256, 256>>>();
    k_gateup<<<dim3(F_ / 64, T_ * TOPK_ / 128, E_), 256, GU_SMEM>>>(guw);
    k_down<<<dim3(D_ / 128, T_ * TOPK_ / 128, E_), 256, GEMM_SMEM>>>(dw);
    k_combine<<<T_, 256>>>(out);
}

// round 12
// speedup vs baseline: 1.0298x; 1.0138x over previous
#include <cuda_runtime.h>
#include <cuda_bf16.h>
#include <math.h>

// ---------------- problem constants ----------------
#define T_    2048
#define D_    2048
#define NQ_   16
#define NKV_  4
#define H_    128
#define E_    16
#define F_    1024
#define TOPK_ 4
#define EPS_  1e-6f
#define SCALE_ 0.088388347648318447f  // 128^-0.5

// ---------------- scratch (device globals; no allocation allowed) ----------------
__device__ float g_hnorm [(size_t)T_ * D_];
__device__ float g_q     [(size_t)T_ * NQ_ * H_];
__device__ float g_k     [(size_t)T_ * NKV_ * H_];
__device__ float g_v     [(size_t)T_ * NKV_ * H_];
__device__ float g_attnout[(size_t)T_ * NQ_ * H_];
__device__ float g_hres  [(size_t)T_ * D_];
__device__ float g_h2    [(size_t)T_ * D_];
__device__ float g_gated [(size_t)T_ * TOPK_ * F_];
__device__ float g_pairout[(size_t)T_ * TOPK_ * D_];

__device__ int   g_topidx[T_ * TOPK_];
__device__ float g_topw  [T_ * TOPK_];
__device__ int   g_counts[E_];
__device__ int   g_offsets[E_];
__device__ int   g_cursor[E_];
__device__ int   g_pair_token[T_ * TOPK_];
__device__ int   g_pair_slot [T_ * TOPK_];

// ---------------- mma / cp.async helpers ----------------
__device__ __forceinline__ void mma_tf32(float* d, const unsigned* a, const unsigned* b) {
    asm volatile(
        "mma.sync.aligned.m16n8k8.row.col.f32.tf32.tf32.f32 "
        "{%0,%1,%2,%3},{%4,%5,%6,%7},{%8,%9},{%0,%1,%2,%3};\n"
        : "+f"(d[0]), "+f"(d[1]), "+f"(d[2]), "+f"(d[3])
        : "r"(a[0]), "r"(a[1]), "r"(a[2]), "r"(a[3]), "r"(b[0]), "r"(b[1]));
}
__device__ __forceinline__ void cpa16(void* smem, const void* g) {
    unsigned s = (unsigned)__cvta_generic_to_shared(smem);
    asm volatile("cp.async.cg.shared.global [%0], [%1], 16;\n" :: "r"(s), "l"(g));
}
__device__ __forceinline__ void cpa_commit() {
    asm volatile("cp.async.commit_group;\n");
}
__device__ __forceinline__ void cpa_wait0() {
    asm volatile("cp.async.wait_group 0;\n");
}
__device__ __forceinline__ void cpa_wait1() {
    asm volatile("cp.async.wait_group 1;\n");
}

// ------- generic tf32 GEMM (NN): BK=16, 3-stage cp.async, ONE barrier/iter ------
// Tile 128x128, 256 threads (8 warps as 2x4). 56.8KB dynamic smem -> 2 CTA/SM.
#define AS_LD 20
#define BS_LD 136
#define GEMM_SMEM ((3 * 128 * AS_LD + 3 * 16 * BS_LD) * 4)
__device__ __forceinline__ void gemm_tf32_body(
    float* dsm,
    const float* __restrict__ A, int lda,
    const float* __restrict__ B, int ldb,
    float* __restrict__ C, int ldc,
    int n0, int K, const float* __restrict__ resid, int mlimit)
{
    float* As = dsm;                        // [3][128][AS_LD]
    float* Bs = dsm + 3 * 128 * AS_LD;      // [3][16][BS_LD]
    const int m0 = blockIdx.y * 128;
    const int tid = threadIdx.x, lane = tid & 31, warp = tid >> 5;
    const int wm = warp >> 2, wn = warp & 3;
    const int gid = lane >> 2, tq = lane & 3;
    float acc[4][4][4] = {};

    const int ar0 = tid >> 1;
    const int ac0 = (tid & 1) * 8;
    int arow = m0 + ar0; if (arow >= mlimit) arow = mlimit - 1;
    const int br0 = tid >> 5;
    const int bc0 = (tid & 31) * 4;

    const int niter = K >> 4;
    auto issue = [&](int it) {
        int k0 = it << 4;
        int st = it % 3;
        float* as = As + st * 128 * AS_LD;
        float* bs = Bs + st * 16 * BS_LD;
        cpa16(&as[ar0 * AS_LD + ac0],     &A[(size_t)arow * lda + k0 + ac0]);
        cpa16(&as[ar0 * AS_LD + ac0 + 4], &A[(size_t)arow * lda + k0 + ac0 + 4]);
        cpa16(&bs[br0 * BS_LD + bc0],       &B[(size_t)(k0 + br0) * ldb + n0 + bc0]);
        cpa16(&bs[(br0 + 8) * BS_LD + bc0], &B[(size_t)(k0 + br0 + 8) * ldb + n0 + bc0]);
        cpa_commit();
    };
    issue(0);
    if (niter > 1) issue(1);

    for (int it = 0; it < niter; it++) {
        if (it + 1 < niter) cpa_wait1(); else cpa_wait0();
        __syncthreads();
        if (it + 2 < niter) issue(it + 2);
        const float* as = As + (it % 3) * 128 * AS_LD;
        const float* bs = Bs + (it % 3) * 16 * BS_LD;
        #pragma unroll
        for (int ks = 0; ks < 16; ks += 8) {
            unsigned a[4][4], b[4][2];
            #pragma unroll
            for (int tm = 0; tm < 4; tm++) {
                int r0 = wm * 64 + tm * 16 + gid;
                a[tm][0] = __float_as_uint(as[r0 * AS_LD + ks + tq]);
                a[tm][1] = __float_as_uint(as[(r0 + 8) * AS_LD + ks + tq]);
                a[tm][2] = __float_as_uint(as[r0 * AS_LD + ks + tq + 4]);
                a[tm][3] = __float_as_uint(as[(r0 + 8) * AS_LD + ks + tq + 4]);
            }
            #pragma unroll
            for (int tn = 0; tn < 4; tn++) {
                int c = wn * 32 + tn * 8 + gid;
                b[tn][0] = __float_as_uint(bs[(ks + tq) * BS_LD + c]);
                b[tn][1] = __float_as_uint(bs[(ks + tq + 4) * BS_LD + c]);
            }
            #pragma unroll
            for (int tm = 0; tm < 4; tm++)
                #pragma unroll
                for (int tn = 0; tn < 4; tn++)
                    mma_tf32(acc[tm][tn], a[tm], b[tn]);
        }
    }
    #pragma unroll
    for (int tm = 0; tm < 4; tm++) {
        int r0 = m0 + wm * 64 + tm * 16 + gid;
        int r1 = r0 + 8;
        #pragma unroll
        for (int tn = 0; tn < 4; tn++) {
            int c0 = n0 + wn * 32 + tn * 8 + 2 * tq;
            if (r0 < mlimit) {
                float v0 = acc[tm][tn][0], v1 = acc[tm][tn][1];
                if (resid) { v0 += resid[(size_t)r0 * ldc + c0]; v1 += resid[(size_t)r0 * ldc + c0 + 1]; }
                C[(size_t)r0 * ldc + c0] = v0; C[(size_t)r0 * ldc + c0 + 1] = v1;
            }
            if (r1 < mlimit) {
                float v2 = acc[tm][tn][2], v3 = acc[tm][tn][3];
                if (resid) { v2 += resid[(size_t)r1 * ldc + c0]; v3 += resid[(size_t)r1 * ldc + c0 + 1]; }
                C[(size_t)r1 * ldc + c0] = v2; C[(size_t)r1 * ldc + c0 + 1] = v3;
            }
        }
    }
}

// ---------------- kernels ----------------

__global__ void k_rmsnorm(const float* __restrict__ x_ext,
                          const float* __restrict__ w)
{
    const int t = blockIdx.x;
    const float* px = x_ext + (size_t)t * D_;
    float* py = g_hnorm + (size_t)t * D_;
    float ss = 0.f;
    for (int d = threadIdx.x; d < D_; d += 256) { float v = px[d]; ss += v * v; }
    __shared__ float red[256];
    red[threadIdx.x] = ss; __syncthreads();
    for (int s = 128; s > 0; s >>= 1) {
        if (threadIdx.x < s) red[threadIdx.x] += red[threadIdx.x + s];
        __syncthreads();
    }
    float r = rsqrtf(red[0] / D_ + EPS_);
    for (int d = threadIdx.x; d < D_; d += 256) py[d] = px[d] * r * w[d];
}

// fused QKV projection: blockIdx.x 0..15 -> q tile, 16..19 -> k, 20..23 -> v
__global__ void __launch_bounds__(256) k_qkv(const float* __restrict__ qw,
                                             const float* __restrict__ kw,
                                             const float* __restrict__ vw)
{
    extern __shared__ float dsm[];
    const int bx = blockIdx.x;
    if (bx < 16) {
        gemm_tf32_body(dsm, g_hnorm, D_, qw, NQ_ * H_, g_q, NQ_ * H_, bx * 128, D_, nullptr, T_);
    } else if (bx < 20) {
        gemm_tf32_body(dsm, g_hnorm, D_, kw, NKV_ * H_, g_k, NKV_ * H_, (bx - 16) * 128, D_, nullptr, T_);
    } else {
        gemm_tf32_body(dsm, g_hnorm, D_, vw, NKV_ * H_, g_v, NKV_ * H_, (bx - 20) * 128, D_, nullptr, T_);
    }
}

// merged q+k norm-rope: blockIdx.y 0..15 = q head, 16..19 = k head
__global__ void k_normrope(const float* __restrict__ qnw,
                           const float* __restrict__ knw,
                           const float* __restrict__ cs,
                           const float* __restrict__ sn)
{
    const int t = blockIdx.x, h = blockIdx.y, d = threadIdx.x; // 128 threads
    const bool isq = (h < NQ_);
    float* p = isq ? (g_q + ((size_t)t * NQ_ + h) * H_)
                   : (g_k + ((size_t)t * NKV_ + (h - NQ_)) * H_);
    const float* w = isq ? qnw : knw;
    float v = p[d];
    __shared__ float sh[128];
    sh[d] = v * v; __syncthreads();
    for (int s = 64; s > 0; s >>= 1) {
        if (d < s) sh[d] += sh[d + s];
        __syncthreads();
    }
    float r = rsqrtf(sh[0] / H_ + EPS_);
    __syncthreads();
    float xn = v * r * w[d];
    sh[d] = xn; __syncthreads();
    float rot = (d < 64) ? -sh[d + 64] : sh[d - 64];
    p[d] = xn * cs[(size_t)t * H_ + d] + rot * sn[(size_t)t * H_ + d];
}

// ---------------- flash attention, tf32 mma, 32 q-rows / 128 threads ------------
// K/V single buffers with ping-pong cp.async (V loads during QK, K+1 during PV).
// smem ~93.6KB -> 2 CTA/SM.
#define FKV_LD 132
#define FPS_LD 68
#define FA_SMEM ((32 * FKV_LD + 64 * FKV_LD + 64 * FKV_LD + 32 * FPS_LD + 3 * 32) * 4)

__global__ void __launch_bounds__(128) k_flashattn()
{
    extern __shared__ float sm[];
    float* Qs    = sm;                       // 32 x FKV_LD
    float* Kb    = Qs + 32 * FKV_LD;         // 64 x FKV_LD
    float* Vb    = Kb + 64 * FKV_LD;         // 64 x FKV_LD
    float* Ps    = Vb + 64 * FKV_LD;         // 32 x FPS_LD
    float* m_s   = Ps + 32 * FPS_LD;
    float* l_s   = m_s + 32;
    float* fac_s = l_s + 32;

    const int by = blockIdx.x;      // q tile of 32 rows (64 tiles)
    const int n  = blockIdx.y;      // head
    const int kv = n >> 2;
    const int tid = threadIdx.x, lane = tid & 31, warp = tid >> 5;
    const int wm = warp >> 1, wn = warp & 1;   // 2x2 warps
    const int gid = lane >> 2, tq = lane & 3;
    const int m0 = by * 32;
    const int ktlast = by >> 1;
    const int dshift = (by & 1) << 5;   // mask: col > row + dshift in last tile

    // Q tile (32x128) via cp.async
    #pragma unroll
    for (int i = 0; i < 8; i++) {
        int idx = tid + 128 * i;
        int r = idx >> 5, c4 = (idx & 31) * 4;
        cpa16(&Qs[r * FKV_LD + c4], &g_q[((size_t)(m0 + r) * NQ_ + n) * H_ + c4]);
    }
    if (tid < 32) { m_s[tid] = -1e30f; l_s[tid] = 0.f; }

    auto issue_k = [&](int kt) {
        int s0 = kt * 64;
        #pragma unroll
        for (int i = 0; i < 16; i++) {
            int idx = tid + 128 * i;
            int r = idx >> 5, c4 = (idx & 31) * 4;
            cpa16(&Kb[r * FKV_LD + c4], &g_k[((size_t)(s0 + r) * NKV_ + kv) * H_ + c4]);
        }
        cpa_commit();
    };
    auto issue_v = [&](int kt) {
        int s0 = kt * 64;
        #pragma unroll
        for (int i = 0; i < 16; i++) {
            int idx = tid + 128 * i;
            int r = idx >> 5, c4 = (idx & 31) * 4;
            cpa16(&Vb[r * FKV_LD + c4], &g_v[((size_t)(s0 + r) * NKV_ + kv) * H_ + c4]);
        }
        cpa_commit();
    };
    issue_k(0);   // also covers the Q loads (same group)

    float o[8][4] = {};

    for (int kt = 0; kt <= ktlast; kt++) {
        cpa_wait0();          // K(kt) (+Q on first iter) landed
        __syncthreads();      // all threads done with PV(kt-1) -> Vb free
        issue_v(kt);          // outstanding: {V(kt)}

        // ---- S = Q K^T, warp tile m16 x n32 ----
        float s[4][4] = {};
        #pragma unroll
        for (int ks = 0; ks < H_; ks += 8) {
            unsigned a[4], b[4][2];
            int r0 = wm * 16 + gid;
            a[0] = __float_as_uint(Qs[r0 * FKV_LD + ks + tq]);
            a[1] = __float_as_uint(Qs[(r0 + 8) * FKV_LD + ks + tq]);
            a[2] = __float_as_uint(Qs[r0 * FKV_LD + ks + tq + 4]);
            a[3] = __float_as_uint(Qs[(r0 + 8) * FKV_LD + ks + tq + 4]);
            #pragma unroll
            for (int f = 0; f < 4; f++) {
                int c = wn * 32 + f * 8 + gid;
                b[f][0] = __float_as_uint(Kb[c * FKV_LD + ks + tq]);
                b[f][1] = __float_as_uint(Kb[c * FKV_LD + ks + tq + 4]);
            }
            #pragma unroll
            for (int f = 0; f < 4; f++) mma_tf32(s[f], a, b[f]);
        }
        {
            int r0 = wm * 16 + gid;
            #pragma unroll
            for (int f = 0; f < 4; f++) {
                int c = wn * 32 + f * 8 + 2 * tq;
                float v0 = s[f][0] * SCALE_, v1 = s[f][1] * SCALE_;
                float v2 = s[f][2] * SCALE_, v3 = s[f][3] * SCALE_;
                if (kt == ktlast) {
                    if (c     > r0 + dshift)     v0 = -1e30f;
                    if (c + 1 > r0 + dshift)     v1 = -1e30f;
                    if (c     > r0 + 8 + dshift) v2 = -1e30f;
                    if (c + 1 > r0 + 8 + dshift) v3 = -1e30f;
                }
                Ps[r0 * FPS_LD + c] = v0;       Ps[r0 * FPS_LD + c + 1] = v1;
                Ps[(r0 + 8) * FPS_LD + c] = v2; Ps[(r0 + 8) * FPS_LD + c + 1] = v3;
            }
        }
        __syncthreads();                 // Ps complete; Kb free
        if (kt < ktlast) issue_k(kt + 1);  // outstanding: {V(kt), K(kt+1)}

        // ---- online softmax: 4 threads per row, 16 cols each ----
        {
            int row = tid >> 2, sub = tid & 3;
            float* pr = Ps + row * FPS_LD + sub * 16;
            float mx = -1e30f;
            #pragma unroll
            for (int i = 0; i < 16; i++) mx = fmaxf(mx, pr[i]);
            mx = fmaxf(mx, __shfl_xor_sync(0xffffffffu, mx, 1));
            mx = fmaxf(mx, __shfl_xor_sync(0xffffffffu, mx, 2));
            float mold = m_s[row];
            float lold = l_s[row];
            float mnew = fmaxf(mold, mx);
            float fac = __expf(mold - mnew);
            float sum = 0.f;
            #pragma unroll
            for (int i = 0; i < 16; i++) {
                float p = __expf(pr[i] - mnew);
                pr[i] = p; sum += p;
            }
            sum += __shfl_xor_sync(0xffffffffu, sum, 1);
            sum += __shfl_xor_sync(0xffffffffu, sum, 2);
            m_s[row] = mnew;
            l_s[row] = lold * fac + sum;
            fac_s[row] = fac;
        }
        if (kt < ktlast) cpa_wait1(); else cpa_wait0();   // V(kt) landed
        __syncthreads();                 // softmax done all rows; V visible

        // rescale O
        {
            float f0 = fac_s[wm * 16 + gid], f1 = fac_s[wm * 16 + gid + 8];
            #pragma unroll
            for (int f = 0; f < 8; f++) {
                o[f][0] *= f0; o[f][1] *= f0; o[f][2] *= f1; o[f][3] *= f1;
            }
        }

        // ---- O += P V, warp tile m16 x n64 ----
        #pragma unroll
        for (int ks = 0; ks < 64; ks += 8) {
            unsigned a[4];
            int r0 = wm * 16 + gid;
            a[0] = __float_as_uint(Ps[r0 * FPS_LD + ks + tq]);
            a[1] = __float_as_uint(Ps[(r0 + 8) * FPS_LD + ks + tq]);
            a[2] = __float_as_uint(Ps[r0 * FPS_LD + ks + tq + 4]);
            a[3] = __float_as_uint(Ps[(r0 + 8) * FPS_LD + ks + tq + 4]);
            #pragma unroll
            for (int f = 0; f < 8; f++) {
                unsigned b[2];
                int c = wn * 64 + f * 8 + gid;
                b[0] = __float_as_uint(Vb[(ks + tq) * FKV_LD + c]);
                b[1] = __float_as_uint(Vb[(ks + tq + 4) * FKV_LD + c]);
                mma_tf32(o[f], a, b);
            }
        }
    }

    {
        float inv0 = 1.f / l_s[wm * 16 + gid];
        float inv1 = 1.f / l_s[wm * 16 + gid + 8];
        int r0 = m0 + wm * 16 + gid;
        int r1 = r0 + 8;
        #pragma unroll
        for (int f = 0; f < 8; f++) {
            int c = wn * 64 + f * 8 + 2 * tq;
            float* d0 = &g_attnout[((size_t)r0 * NQ_ + n) * H_ + c];
            float* d1 = &g_attnout[((size_t)r1 * NQ_ + n) * H_ + c];
            d0[0] = o[f][0] * inv0; d0[1] = o[f][1] * inv0;
            d1[0] = o[f][2] * inv1; d1[1] = o[f][3] * inv1;
        }
    }
}

__global__ void __launch_bounds__(256) k_oproj(const float* __restrict__ W,
                                               const float* __restrict__ resid)
{
    extern __shared__ float dsm[];
    gemm_tf32_body(dsm, g_attnout, NQ_ * H_, W, D_, g_hres, D_,
                   blockIdx.x * 128, NQ_ * H_, resid, T_);
}

__global__ void k_zero()
{
    if (threadIdx.x < E_) g_counts[threadIdx.x] = 0;
}

// fused post-attn RMSNorm + router (per token): g_hres -> g_h2, topk, counts
__global__ void k_rms_router(const float* __restrict__ pln,
                             const float* __restrict__ gate_w)
{
    const int t = blockIdx.x, tid = threadIdx.x;   // 256 threads
    const float* px = g_hres + (size_t)t * D_;
    float* py = g_h2 + (size_t)t * D_;
    float xv[8];
    float ss = 0.f;
    #pragma unroll
    for (int i = 0; i < 8; i++) {
        float v = px[tid + 256 * i];
        xv[i] = v; ss += v * v;
    }
    __shared__ float red[256];
    red[tid] = ss; __syncthreads();
    for (int s = 128; s > 0; s >>= 1) {
        if (tid < s) red[tid] += red[tid + s];
        __syncthreads();
    }
    const float r = rsqrtf(red[0] / D_ + EPS_);

    float acc[E_];
    #pragma unroll
    for (int e = 0; e < E_; e++) acc[e] = 0.f;
    #pragma unroll
    for (int i = 0; i < 8; i++) {
        int d = tid + 256 * i;
        float y = xv[i] * r * pln[d];
        py[d] = y;
        const float* gw = gate_w + (size_t)d * E_;
        #pragma unroll
        for (int e = 0; e < E_; e++) acc[e] = fmaf(y, gw[e], acc[e]);
    }
    __shared__ float sh[256 * E_];
    #pragma unroll
    for (int e = 0; e < E_; e++) sh[tid * E_ + e] = acc[e];
    __syncthreads();
    for (int s = 128; s > 0; s >>= 1) {
        if (tid < s)
            #pragma unroll
            for (int e = 0; e < E_; e++) sh[tid * E_ + e] += sh[(tid + s) * E_ + e];
        __syncthreads();
    }
    if (tid == 0) {
        float p[E_];
        float m = -1e30f;
        for (int e = 0; e < E_; e++) m = fmaxf(m, sh[e]);
        float sum = 0.f;
        for (int e = 0; e < E_; e++) { p[e] = __expf(sh[e] - m); sum += p[e]; }
        float invs = 1.f / sum;
        for (int e = 0; e < E_; e++) p[e] *= invs;
        int idx[TOPK_]; float wv[TOPK_]; float wsum = 0.f;
        for (int k = 0; k < TOPK_; k++) {
            int best = 0; float bv = p[0];
            for (int e = 1; e < E_; e++) if (p[e] > bv) { bv = p[e]; best = e; }
            idx[k] = best; wv[k] = bv; wsum += bv; p[best] = -1.f;
        }
        float invw = 1.f / wsum;
        for (int k = 0; k < TOPK_; k++) {
            g_topidx[t * TOPK_ + k] = idx[k];
            g_topw[t * TOPK_ + k] = wv[k] * invw;
            atomicAdd(&g_counts[idx[k]], 1);
        }
    }
}

__global__ void k_scan()
{
    int off = 0;
    for (int e = 0; e < E_; e++) {
        g_offsets[e] = off;
        off += g_counts[e];
        g_cursor[e] = 0;
    }
}

__global__ void k_assign()
{
    int i = blockIdx.x * blockDim.x + threadIdx.x;
    if (i >= T_ * TOPK_) return;
    int e = g_topidx[i];
    int slot = g_offsets[e] + atomicAdd(&g_cursor[e], 1);
    g_pair_token[slot] = i >> 2;
    g_pair_slot[i] = slot;
}

// ------- MoE gate_up: BK=16, 3-stage, gate+up packed in ONE B buffer ------------
// B stage = [16][BS_LD]: gate cols [0,64), up cols [64,128). 56.8KB -> 2 CTA/SM.
#define GU_SMEM ((3 * 128 * AS_LD + 3 * 16 * BS_LD) * 4)
__global__ void __launch_bounds__(256) k_gateup(const float* __restrict__ gate_up_w)
{
    extern __shared__ float dsm[];
    float* As = dsm;                                 // [3][128][AS_LD]
    float* Bs = dsm + 3 * 128 * AS_LD;               // [3][16][BS_LD]
    __shared__ int rowTok[128];

    const int e = blockIdx.z;
    const int cnt = g_counts[e];
    const int m0 = blockIdx.y * 128;
    if (m0 >= cnt) return;
    const int base = g_offsets[e];
    const int n0 = blockIdx.x * 64;
    const float* B = gate_up_w + (size_t)e * D_ * (2 * F_);

    const int tid = threadIdx.x, lane = tid & 31, warp = tid >> 5;
    const int wm = warp >> 2, wn = warp & 3;
    const int gid = lane >> 2, tq = lane & 3;

    if (tid < 128) {
        int r = m0 + tid;
        rowTok[tid] = (r < cnt) ? g_pair_token[base + r] : g_pair_token[base];
    }
    __syncthreads();

    const int ar0 = tid >> 1;
    const int ac0 = (tid & 1) * 8;
    const size_t arow = (size_t)rowTok[ar0] * D_;
    const int br0 = tid >> 4;          // 0..15
    const int bc0 = (tid & 15) * 4;    // 0..60

    float ag[4][2][4] = {}, au[4][2][4] = {};

    const int niter = D_ >> 4;
    auto issue = [&](int it) {
        int k0 = it << 4;
        int st = it % 3;
        float* as = As + st * 128 * AS_LD;
        float* bs = Bs + st * 16 * BS_LD;
        cpa16(&as[ar0 * AS_LD + ac0],     &g_h2[arow + k0 + ac0]);
        cpa16(&as[ar0 * AS_LD + ac0 + 4], &g_h2[arow + k0 + ac0 + 4]);
        const float* brow = B + (size_t)(k0 + br0) * (2 * F_);
        cpa16(&bs[br0 * BS_LD + bc0],      &brow[n0 + bc0]);        // gate -> cols [0,64)
        cpa16(&bs[br0 * BS_LD + 64 + bc0], &brow[F_ + n0 + bc0]);   // up   -> cols [64,128)
        cpa_commit();
    };
    issue(0);
    issue(1);

    for (int it = 0; it < niter; it++) {
        if (it + 1 < niter) cpa_wait1(); else cpa_wait0();
        __syncthreads();
        if (it + 2 < niter) issue(it + 2);
        const float* as = As + (it % 3) * 128 * AS_LD;
        const float* bs = Bs + (it % 3) * 16 * BS_LD;
        #pragma unroll
        for (int ks = 0; ks < 16; ks += 8) {
            unsigned a[4][4], bg[2][2], bu[2][2];
            #pragma unroll
            for (int tm = 0; tm < 4; tm++) {
                int r0 = wm * 64 + tm * 16 + gid;
                a[tm][0] = __float_as_uint(as[r0 * AS_LD + ks + tq]);
                a[tm][1] = __float_as_uint(as[(r0 + 8) * AS_LD + ks + tq]);
                a[tm][2] = __float_as_uint(as[r0 * AS_LD + ks + tq + 4]);
                a[tm][3] = __float_as_uint(as[(r0 + 8) * AS_LD + ks + tq + 4]);
            }
            #pragma unroll
            for (int tn = 0; tn < 2; tn++) {
                int c = wn * 16 + tn * 8 + gid;
                bg[tn][0] = __float_as_uint(bs[(ks + tq) * BS_LD + c]);
                bg[tn][1] = __float_as_uint(bs[(ks + tq + 4) * BS_LD + c]);
                bu[tn][0] = __float_as_uint(bs[(ks + tq) * BS_LD + 64 + c]);
                bu[tn][1] = __float_as_uint(bs[(ks + tq + 4) * BS_LD + 64 + c]);
            }
            #pragma unroll
            for (int tm = 0; tm < 4; tm++)
                #pragma unroll
                for (int tn = 0; tn < 2; tn++) {
                    mma_tf32(ag[tm][tn], a[tm], bg[tn]);
                    mma_tf32(au[tm][tn], a[tm], bu[tn]);
                }
        }
    }
    #pragma unroll
    for (int tm = 0; tm < 4; tm++) {
        int r0 = m0 + wm * 64 + tm * 16 + gid;
        int r1 = r0 + 8;
        #pragma unroll
        for (int tn = 0; tn < 2; tn++) {
            int c0 = n0 + wn * 16 + tn * 8 + 2 * tq;
            if (r0 < cnt) {
                float g0 = ag[tm][tn][0], u0 = au[tm][tn][0];
                float g1 = ag[tm][tn][1], u1 = au[tm][tn][1];
                g_gated[(size_t)(base + r0) * F_ + c0]     = u0 * (g0 / (1.f + __expf(-g0)));
                g_gated[(size_t)(base + r0) * F_ + c0 + 1] = u1 * (g1 / (1.f + __expf(-g1)));
            }
            if (r1 < cnt) {
                float g2 = ag[tm][tn][2], u2 = au[tm][tn][2];
                float g3 = ag[tm][tn][3], u3 = au[tm][tn][3];
                g_gated[(size_t)(base + r1) * F_ + c0]     = u2 * (g2 / (1.f + __expf(-g2)));
                g_gated[(size_t)(base + r1) * F_ + c0 + 1] = u3 * (g3 / (1.f + __expf(-g3)));
            }
        }
    }
}

__global__ void __launch_bounds__(256) k_down(const float* __restrict__ down_w)
{
    extern __shared__ float dsm[];
    const int e = blockIdx.z;
    const int cnt = g_counts[e];
    if ((int)blockIdx.y * 128 >= cnt) return;
    const int base = g_offsets[e];
    gemm_tf32_body(dsm, g_gated + (size_t)base * F_, F_,
                   down_w + (size_t)e * F_ * D_, D_,
                   g_pairout + (size_t)base * D_, D_,
                   blockIdx.x * 128, F_, nullptr, cnt);
}

__global__ void k_combine(float* __restrict__ out)
{
    const int t = blockIdx.x;
    const int s0 = g_pair_slot[t * 4 + 0], s1 = g_pair_slot[t * 4 + 1];
    const int s2 = g_pair_slot[t * 4 + 2], s3 = g_pair_slot[t * 4 + 3];
    const float w0 = g_topw[t * 4 + 0], w1 = g_topw[t * 4 + 1];
    const float w2 = g_topw[t * 4 + 2], w3 = g_topw[t * 4 + 3];
    const float* p0 = g_pairout + (size_t)s0 * D_;
    const float* p1 = g_pairout + (size_t)s1 * D_;
    const float* p2 = g_pairout + (size_t)s2 * D_;
    const float* p3 = g_pairout + (size_t)s3 * D_;
    const float* hr = g_hres + (size_t)t * D_;
    float* o = out + (size_t)t * D_;
    for (int d = threadIdx.x; d < D_; d += 256)
        o[d] = hr[d] + w0 * p0[d] + w1 * p1[d] + w2 * p2[d] + w3 * p3[d];
}

// ---------------- launch ----------------
extern "C" void kernel_launch(void* const* d_in, const int* in_sizes, int n_in,
                              void* d_out, int out_size)
{
    const float* hidden = (const float*)d_in[0];
    const float* cosp   = (const float*)d_in[1];
    const float* sinp   = (const float*)d_in[2];
    const float* iln    = (const float*)d_in[4];
    const float* pln    = (const float*)d_in[5];
    const float* qw     = (const float*)d_in[6];
    const float* kw     = (const float*)d_in[7];
    const float* vw     = (const float*)d_in[8];
    const float* ow     = (const float*)d_in[9];
    const float* qnw    = (const float*)d_in[10];
    const float* knw    = (const float*)d_in[11];
    const float* gw     = (const float*)d_in[12];
    const float* guw    = (const float*)d_in[13];
    const float* dw     = (const float*)d_in[14];
    float* out = (float*)d_out;

    static bool attr_set = false;
    if (!attr_set) {
        cudaFuncSetAttribute(k_flashattn, cudaFuncAttributeMaxDynamicSharedMemorySize, FA_SMEM);
        cudaFuncSetAttribute(k_qkv,    cudaFuncAttributeMaxDynamicSharedMemorySize, GEMM_SMEM);
        cudaFuncSetAttribute(k_oproj,  cudaFuncAttributeMaxDynamicSharedMemorySize, GEMM_SMEM);
        cudaFuncSetAttribute(k_down,   cudaFuncAttributeMaxDynamicSharedMemorySize, GEMM_SMEM);
        cudaFuncSetAttribute(k_gateup, cudaFuncAttributeMaxDynamicSharedMemorySize, GU_SMEM);
        attr_set = true;
    }

    k_rmsnorm<<<T_, 256>>>(hidden, iln);
    k_qkv<<<dim3(24, T_ / 128), 256, GEMM_SMEM>>>(qw, kw, vw);
    k_normrope<<<dim3(T_, NQ_ + NKV_), 128>>>(qnw, knw, cosp, sinp);
    k_flashattn<<<dim3(T_ / 32, NQ_), 128, FA_SMEM>>>();
    k_oproj<<<dim3(D_ / 128, T_ / 128), 256, GEMM_SMEM>>>(ow, hidden);
    k_zero<<<1, 32>>>();
    k_rms_router<<<T_, 256>>>(pln, gw);
    k_scan<<<1, 1>>>();
    k_assign<<<(T_ * TOPK_ + 255) / 256, 256>>>();
    k_gateup<<<dim3(F_ / 64, T_ * TOPK_ / 128, E_), 256, GU_SMEM>>>(guw);
    k_down<<<dim3(D_ / 128, T_ * TOPK_ / 128, E_), 256, GEMM_SMEM>>>(dw);
    k_combine<<<T_, 256>>>(out);
}

// round 13
// speedup vs baseline: 1.0451x; 1.0149x over previous
#include <cuda_runtime.h>
#include <cuda_bf16.h>
#include <math.h>

// ---------------- problem constants ----------------
#define T_    2048
#define D_    2048
#define NQ_   16
#define NKV_  4
#define H_    128
#define E_    16
#define F_    1024
#define TOPK_ 4
#define EPS_  1e-6f
#define SCALE_ 0.088388347648318447f  // 128^-0.5

// ---------------- scratch (device globals; no allocation allowed) ----------------
__device__ float g_hnorm [(size_t)T_ * D_];
__device__ float g_q     [(size_t)T_ * NQ_ * H_];
__device__ float g_k     [(size_t)T_ * NKV_ * H_];
__device__ float g_v     [(size_t)T_ * NKV_ * H_];
__device__ float g_attnout[(size_t)T_ * NQ_ * H_];
__device__ float g_hres  [(size_t)T_ * D_];
__device__ float g_h2    [(size_t)T_ * D_];
__device__ float g_gated [(size_t)T_ * TOPK_ * F_];
__device__ float g_pairout[(size_t)T_ * TOPK_ * D_];

__device__ int   g_topidx[T_ * TOPK_];
__device__ float g_topw  [T_ * TOPK_];
__device__ int   g_counts[E_];
__device__ int   g_offsets[E_];
__device__ int   g_cursor[E_];
__device__ int   g_pair_token[T_ * TOPK_];
__device__ int   g_pair_slot [T_ * TOPK_];

// ---------------- mma / cp.async helpers ----------------
__device__ __forceinline__ void mma_tf32(float* d, const unsigned* a, const unsigned* b) {
    asm volatile(
        "mma.sync.aligned.m16n8k8.row.col.f32.tf32.tf32.f32 "
        "{%0,%1,%2,%3},{%4,%5,%6,%7},{%8,%9},{%0,%1,%2,%3};\n"
        : "+f"(d[0]), "+f"(d[1]), "+f"(d[2]), "+f"(d[3])
        : "r"(a[0]), "r"(a[1]), "r"(a[2]), "r"(a[3]), "r"(b[0]), "r"(b[1]));
}
__device__ __forceinline__ void cpa16(void* smem, const void* g) {
    unsigned s = (unsigned)__cvta_generic_to_shared(smem);
    asm volatile("cp.async.cg.shared.global [%0], [%1], 16;\n" :: "r"(s), "l"(g));
}
__device__ __forceinline__ void cpa_commit() {
    asm volatile("cp.async.commit_group;\n");
}
__device__ __forceinline__ void cpa_wait0() {
    asm volatile("cp.async.wait_group 0;\n");
}
__device__ __forceinline__ void cpa_wait1() {
    asm volatile("cp.async.wait_group 1;\n");
}

// ------- generic tf32 GEMM (NN): BK=16, 3-stage cp.async, ONE barrier/iter ------
// Tile 128x128, 256 threads (8 warps as 2x4). 56.8KB dynamic smem -> 2 CTA/SM.
#define AS_LD 20
#define BS_LD 136
#define GEMM_SMEM ((3 * 128 * AS_LD + 3 * 16 * BS_LD) * 4)
__device__ __forceinline__ void gemm_tf32_body(
    float* dsm,
    const float* __restrict__ A, int lda,
    const float* __restrict__ B, int ldb,
    float* __restrict__ C, int ldc,
    int n0, int K, const float* __restrict__ resid, int mlimit)
{
    float* As = dsm;                        // [3][128][AS_LD]
    float* Bs = dsm + 3 * 128 * AS_LD;      // [3][16][BS_LD]
    const int m0 = blockIdx.y * 128;
    const int tid = threadIdx.x, lane = tid & 31, warp = tid >> 5;
    const int wm = warp >> 2, wn = warp & 3;
    const int gid = lane >> 2, tq = lane & 3;
    float acc[4][4][4] = {};

    const int ar0 = tid >> 1;
    const int ac0 = (tid & 1) * 8;
    int arow = m0 + ar0; if (arow >= mlimit) arow = mlimit - 1;
    const int br0 = tid >> 5;
    const int bc0 = (tid & 31) * 4;

    const int niter = K >> 4;
    auto issue = [&](int it) {
        int k0 = it << 4;
        int st = it % 3;
        float* as = As + st * 128 * AS_LD;
        float* bs = Bs + st * 16 * BS_LD;
        cpa16(&as[ar0 * AS_LD + ac0],     &A[(size_t)arow * lda + k0 + ac0]);
        cpa16(&as[ar0 * AS_LD + ac0 + 4], &A[(size_t)arow * lda + k0 + ac0 + 4]);
        cpa16(&bs[br0 * BS_LD + bc0],       &B[(size_t)(k0 + br0) * ldb + n0 + bc0]);
        cpa16(&bs[(br0 + 8) * BS_LD + bc0], &B[(size_t)(k0 + br0 + 8) * ldb + n0 + bc0]);
        cpa_commit();
    };
    issue(0);
    if (niter > 1) issue(1);

    for (int it = 0; it < niter; it++) {
        if (it + 1 < niter) cpa_wait1(); else cpa_wait0();
        __syncthreads();
        if (it + 2 < niter) issue(it + 2);
        const float* as = As + (it % 3) * 128 * AS_LD;
        const float* bs = Bs + (it % 3) * 16 * BS_LD;
        #pragma unroll
        for (int ks = 0; ks < 16; ks += 8) {
            unsigned a[4][4], b[4][2];
            #pragma unroll
            for (int tm = 0; tm < 4; tm++) {
                int r0 = wm * 64 + tm * 16 + gid;
                a[tm][0] = __float_as_uint(as[r0 * AS_LD + ks + tq]);
                a[tm][1] = __float_as_uint(as[(r0 + 8) * AS_LD + ks + tq]);
                a[tm][2] = __float_as_uint(as[r0 * AS_LD + ks + tq + 4]);
                a[tm][3] = __float_as_uint(as[(r0 + 8) * AS_LD + ks + tq + 4]);
            }
            #pragma unroll
            for (int tn = 0; tn < 4; tn++) {
                int c = wn * 32 + tn * 8 + gid;
                b[tn][0] = __float_as_uint(bs[(ks + tq) * BS_LD + c]);
                b[tn][1] = __float_as_uint(bs[(ks + tq + 4) * BS_LD + c]);
            }
            #pragma unroll
            for (int tm = 0; tm < 4; tm++)
                #pragma unroll
                for (int tn = 0; tn < 4; tn++)
                    mma_tf32(acc[tm][tn], a[tm], b[tn]);
        }
    }
    #pragma unroll
    for (int tm = 0; tm < 4; tm++) {
        int r0 = m0 + wm * 64 + tm * 16 + gid;
        int r1 = r0 + 8;
        #pragma unroll
        for (int tn = 0; tn < 4; tn++) {
            int c0 = n0 + wn * 32 + tn * 8 + 2 * tq;
            if (r0 < mlimit) {
                float v0 = acc[tm][tn][0], v1 = acc[tm][tn][1];
                if (resid) { v0 += resid[(size_t)r0 * ldc + c0]; v1 += resid[(size_t)r0 * ldc + c0 + 1]; }
                C[(size_t)r0 * ldc + c0] = v0; C[(size_t)r0 * ldc + c0 + 1] = v1;
            }
            if (r1 < mlimit) {
                float v2 = acc[tm][tn][2], v3 = acc[tm][tn][3];
                if (resid) { v2 += resid[(size_t)r1 * ldc + c0]; v3 += resid[(size_t)r1 * ldc + c0 + 1]; }
                C[(size_t)r1 * ldc + c0] = v2; C[(size_t)r1 * ldc + c0 + 1] = v3;
            }
        }
    }
}

// ---------------- kernels ----------------

__global__ void k_rmsnorm(const float* __restrict__ x_ext,
                          const float* __restrict__ w)
{
    const int t = blockIdx.x;
    const float* px = x_ext + (size_t)t * D_;
    float* py = g_hnorm + (size_t)t * D_;
    float ss = 0.f;
    for (int d = threadIdx.x; d < D_; d += 256) { float v = px[d]; ss += v * v; }
    __shared__ float red[256];
    red[threadIdx.x] = ss; __syncthreads();
    for (int s = 128; s > 0; s >>= 1) {
        if (threadIdx.x < s) red[threadIdx.x] += red[threadIdx.x + s];
        __syncthreads();
    }
    float r = rsqrtf(red[0] / D_ + EPS_);
    for (int d = threadIdx.x; d < D_; d += 256) py[d] = px[d] * r * w[d];
}

// fused QKV projection: blockIdx.x 0..15 -> q tile, 16..19 -> k, 20..23 -> v
__global__ void __launch_bounds__(256) k_qkv(const float* __restrict__ qw,
                                             const float* __restrict__ kw,
                                             const float* __restrict__ vw)
{
    extern __shared__ float dsm[];
    const int bx = blockIdx.x;
    if (bx < 16) {
        gemm_tf32_body(dsm, g_hnorm, D_, qw, NQ_ * H_, g_q, NQ_ * H_, bx * 128, D_, nullptr, T_);
    } else if (bx < 20) {
        gemm_tf32_body(dsm, g_hnorm, D_, kw, NKV_ * H_, g_k, NKV_ * H_, (bx - 16) * 128, D_, nullptr, T_);
    } else {
        gemm_tf32_body(dsm, g_hnorm, D_, vw, NKV_ * H_, g_v, NKV_ * H_, (bx - 20) * 128, D_, nullptr, T_);
    }
}

// merged q+k norm-rope: blockIdx.y 0..15 = q head, 16..19 = k head
__global__ void k_normrope(const float* __restrict__ qnw,
                           const float* __restrict__ knw,
                           const float* __restrict__ cs,
                           const float* __restrict__ sn)
{
    const int t = blockIdx.x, h = blockIdx.y, d = threadIdx.x; // 128 threads
    const bool isq = (h < NQ_);
    float* p = isq ? (g_q + ((size_t)t * NQ_ + h) * H_)
                   : (g_k + ((size_t)t * NKV_ + (h - NQ_)) * H_);
    const float* w = isq ? qnw : knw;
    float v = p[d];
    __shared__ float sh[128];
    sh[d] = v * v; __syncthreads();
    for (int s = 64; s > 0; s >>= 1) {
        if (d < s) sh[d] += sh[d + s];
        __syncthreads();
    }
    float r = rsqrtf(sh[0] / H_ + EPS_);
    __syncthreads();
    float xn = v * r * w[d];
    sh[d] = xn; __syncthreads();
    float rot = (d < 64) ? -sh[d + 64] : sh[d - 64];
    p[d] = xn * cs[(size_t)t * H_ + d] + rot * sn[(size_t)t * H_ + d];
}

// ---------------- flash attention: 2 GQA heads per CTA, tf32 mma ----------------
// 256 threads: warps 0-3 = head hb, warps 4-7 = head hb+1 (same kv head, same
// 32 q-rows -> identical causal shape, shared K/V tiles). Q/K/V swizzled LD=128.
// smem = 3*64*128*4 + 64*68*4 = 113KB -> 2 CTA/SM. Stats live in Ps cols 64..66.
#define FPS_LD 68
#define FA_SMEM ((3 * 64 * 128 + 64 * FPS_LD) * 4)
// swizzled float offset within a [rows][128] tile
#define SWF(row, col) (((row) << 7) + (((((col) >> 2) ^ ((row) & 7)) << 2) | ((col) & 3)))

__global__ void __launch_bounds__(256) k_flashattn()
{
    extern __shared__ float sm[];
    float* Qs = sm;                  // 64 x 128 (2 head-tiles) swizzled
    float* Kb = Qs + 64 * 128;       // 64 x 128 swizzled
    float* Vb = Kb + 64 * 128;       // 64 x 128 swizzled
    float* Ps = Vb + 64 * 128;       // 64 x FPS_LD ; col64=m, col65=l, col66=fac

    const int by = blockIdx.x;          // row tile of 32 (64 tiles)
    const int kv = blockIdx.y;          // 0..3
    const int hb = kv * 4 + blockIdx.z * 2;   // head base for this CTA
    const int tid = threadIdx.x, lane = tid & 31, warp = tid >> 5;
    const int wg = warp >> 2;           // 0/1: which head
    const int w2 = warp & 3;
    const int wm = w2 >> 1, wn = w2 & 1;
    const int gid = lane >> 2, tq = lane & 3;
    const int m0 = by * 32;
    const int ktlast = by >> 1;
    const int dshift = (by & 1) << 5;
    const int n = hb + wg;

    // Q: two 32x128 head tiles (rows 0-31 head hb, 32-63 head hb+1)
    #pragma unroll
    for (int i = 0; i < 8; i++) {
        int idx = tid + 256 * i;            // 2048 chunks
        int r = idx >> 5, c4 = (idx & 31) * 4;
        int head = hb + (r >> 5);
        int row = m0 + (r & 31);
        cpa16(&Qs[SWF(r, c4)], &g_q[((size_t)row * NQ_ + head) * H_ + c4]);
    }
    if (tid < 64) { Ps[tid * FPS_LD + 64] = -1e30f; Ps[tid * FPS_LD + 65] = 0.f; }

    auto issue_k = [&](int kt) {
        int s0 = kt * 64;
        #pragma unroll
        for (int i = 0; i < 8; i++) {
            int idx = tid + 256 * i;
            int r = idx >> 5, c4 = (idx & 31) * 4;
            cpa16(&Kb[SWF(r, c4)], &g_k[((size_t)(s0 + r) * NKV_ + kv) * H_ + c4]);
        }
        cpa_commit();
    };
    auto issue_v = [&](int kt) {
        int s0 = kt * 64;
        #pragma unroll
        for (int i = 0; i < 8; i++) {
            int idx = tid + 256 * i;
            int r = idx >> 5, c4 = (idx & 31) * 4;
            cpa16(&Vb[SWF(r, c4)], &g_v[((size_t)(s0 + r) * NKV_ + kv) * H_ + c4]);
        }
        cpa_commit();
    };
    issue_k(0);   // also commits the Q loads (same group)

    float o[8][4] = {};
    const int qr = wg * 32 + wm * 16 + gid;   // Qs/Ps row for this thread's fragment
    const int rmask = wm * 16 + gid;          // row within 32 (for causal mask)

    for (int kt = 0; kt <= ktlast; kt++) {
        cpa_wait0();          // K(kt) (+Q on first iter) landed
        __syncthreads();      // PV(kt-1) done -> Vb free
        issue_v(kt);          // outstanding: {V(kt)}

        // ---- S = Q K^T, per-head warp tile m16 x n32 ----
        float s[4][4] = {};
        #pragma unroll
        for (int ks = 0; ks < H_; ks += 8) {
            unsigned a[4], b[4][2];
            a[0] = __float_as_uint(Qs[SWF(qr, ks + tq)]);
            a[1] = __float_as_uint(Qs[SWF(qr + 8, ks + tq)]);
            a[2] = __float_as_uint(Qs[SWF(qr, ks + tq + 4)]);
            a[3] = __float_as_uint(Qs[SWF(qr + 8, ks + tq + 4)]);
            #pragma unroll
            for (int f = 0; f < 4; f++) {
                int c = wn * 32 + f * 8 + gid;
                b[f][0] = __float_as_uint(Kb[SWF(c, ks + tq)]);
                b[f][1] = __float_as_uint(Kb[SWF(c, ks + tq + 4)]);
            }
            #pragma unroll
            for (int f = 0; f < 4; f++) mma_tf32(s[f], a, b[f]);
        }
        {
            #pragma unroll
            for (int f = 0; f < 4; f++) {
                int c = wn * 32 + f * 8 + 2 * tq;
                float v0 = s[f][0] * SCALE_, v1 = s[f][1] * SCALE_;
                float v2 = s[f][2] * SCALE_, v3 = s[f][3] * SCALE_;
                if (kt == ktlast) {
                    if (c     > rmask + dshift)     v0 = -1e30f;
                    if (c + 1 > rmask + dshift)     v1 = -1e30f;
                    if (c     > rmask + 8 + dshift) v2 = -1e30f;
                    if (c + 1 > rmask + 8 + dshift) v3 = -1e30f;
                }
                Ps[qr * FPS_LD + c] = v0;       Ps[qr * FPS_LD + c + 1] = v1;
                Ps[(qr + 8) * FPS_LD + c] = v2; Ps[(qr + 8) * FPS_LD + c + 1] = v3;
            }
        }
        __syncthreads();                   // Ps complete; Kb free
        if (kt < ktlast) issue_k(kt + 1);  // outstanding: {V(kt), K(kt+1)}

        // ---- online softmax: 4 threads per row, 64 rows (2 heads) ----
        {
            int row = tid >> 2, sub = tid & 3;
            float* pr = Ps + row * FPS_LD + sub * 16;
            float* st = Ps + row * FPS_LD;
            float mx = -1e30f;
            #pragma unroll
            for (int i = 0; i < 16; i++) mx = fmaxf(mx, pr[i]);
            mx = fmaxf(mx, __shfl_xor_sync(0xffffffffu, mx, 1));
            mx = fmaxf(mx, __shfl_xor_sync(0xffffffffu, mx, 2));
            float mold = st[64];
            float lold = st[65];
            float mnew = fmaxf(mold, mx);
            float fac = __expf(mold - mnew);
            float sum = 0.f;
            #pragma unroll
            for (int i = 0; i < 16; i++) {
                float p = __expf(pr[i] - mnew);
                pr[i] = p; sum += p;
            }
            sum += __shfl_xor_sync(0xffffffffu, sum, 1);
            sum += __shfl_xor_sync(0xffffffffu, sum, 2);
            if (sub == 0) {
                st[64] = mnew;
                st[65] = lold * fac + sum;
                st[66] = fac;
            }
        }
        if (kt < ktlast) cpa_wait1(); else cpa_wait0();   // V(kt) landed
        __syncthreads();

        // rescale O
        {
            float f0 = Ps[qr * FPS_LD + 66], f1 = Ps[(qr + 8) * FPS_LD + 66];
            #pragma unroll
            for (int f = 0; f < 8; f++) {
                o[f][0] *= f0; o[f][1] *= f0; o[f][2] *= f1; o[f][3] *= f1;
            }
        }

        // ---- O += P V, per-head warp tile m16 x n64 ----
        #pragma unroll
        for (int ks = 0; ks < 64; ks += 8) {
            unsigned a[4];
            a[0] = __float_as_uint(Ps[qr * FPS_LD + ks + tq]);
            a[1] = __float_as_uint(Ps[(qr + 8) * FPS_LD + ks + tq]);
            a[2] = __float_as_uint(Ps[qr * FPS_LD + ks + tq + 4]);
            a[3] = __float_as_uint(Ps[(qr + 8) * FPS_LD + ks + tq + 4]);
            #pragma unroll
            for (int f = 0; f < 8; f++) {
                unsigned b[2];
                int c = wn * 64 + f * 8 + gid;
                b[0] = __float_as_uint(Vb[SWF(ks + tq, c)]);
                b[1] = __float_as_uint(Vb[SWF(ks + tq + 4, c)]);
                mma_tf32(o[f], a, b);
            }
        }
    }

    {
        float inv0 = 1.f / Ps[qr * FPS_LD + 65];
        float inv1 = 1.f / Ps[(qr + 8) * FPS_LD + 65];
        int r0 = m0 + wm * 16 + gid;
        int r1 = r0 + 8;
        #pragma unroll
        for (int f = 0; f < 8; f++) {
            int c = wn * 64 + f * 8 + 2 * tq;
            float* d0 = &g_attnout[((size_t)r0 * NQ_ + n) * H_ + c];
            float* d1 = &g_attnout[((size_t)r1 * NQ_ + n) * H_ + c];
            d0[0] = o[f][0] * inv0; d0[1] = o[f][1] * inv0;
            d1[0] = o[f][2] * inv1; d1[1] = o[f][3] * inv1;
        }
    }
}

__global__ void __launch_bounds__(256) k_oproj(const float* __restrict__ W,
                                               const float* __restrict__ resid)
{
    extern __shared__ float dsm[];
    gemm_tf32_body(dsm, g_attnout, NQ_ * H_, W, D_, g_hres, D_,
                   blockIdx.x * 128, NQ_ * H_, resid, T_);
}

__global__ void k_zero()
{
    if (threadIdx.x < E_) g_counts[threadIdx.x] = 0;
}

// fused post-attn RMSNorm + router (per token): g_hres -> g_h2, topk, counts
__global__ void k_rms_router(const float* __restrict__ pln,
                             const float* __restrict__ gate_w)
{
    const int t = blockIdx.x, tid = threadIdx.x;   // 256 threads
    const float* px = g_hres + (size_t)t * D_;
    float* py = g_h2 + (size_t)t * D_;
    float xv[8];
    float ss = 0.f;
    #pragma unroll
    for (int i = 0; i < 8; i++) {
        float v = px[tid + 256 * i];
        xv[i] = v; ss += v * v;
    }
    __shared__ float red[256];
    red[tid] = ss; __syncthreads();
    for (int s = 128; s > 0; s >>= 1) {
        if (tid < s) red[tid] += red[tid + s];
        __syncthreads();
    }
    const float r = rsqrtf(red[0] / D_ + EPS_);

    float acc[E_];
    #pragma unroll
    for (int e = 0; e < E_; e++) acc[e] = 0.f;
    #pragma unroll
    for (int i = 0; i < 8; i++) {
        int d = tid + 256 * i;
        float y = xv[i] * r * pln[d];
        py[d] = y;
        const float* gw = gate_w + (size_t)d * E_;
        #pragma unroll
        for (int e = 0; e < E_; e++) acc[e] = fmaf(y, gw[e], acc[e]);
    }
    __shared__ float sh[256 * E_];
    #pragma unroll
    for (int e = 0; e < E_; e++) sh[tid * E_ + e] = acc[e];
    __syncthreads();
    for (int s = 128; s > 0; s >>= 1) {
        if (tid < s)
            #pragma unroll
            for (int e = 0; e < E_; e++) sh[tid * E_ + e] += sh[(tid + s) * E_ + e];
        __syncthreads();
    }
    if (tid == 0) {
        float p[E_];
        float m = -1e30f;
        for (int e = 0; e < E_; e++) m = fmaxf(m, sh[e]);
        float sum = 0.f;
        for (int e = 0; e < E_; e++) { p[e] = __expf(sh[e] - m); sum += p[e]; }
        float invs = 1.f / sum;
        for (int e = 0; e < E_; e++) p[e] *= invs;
        int idx[TOPK_]; float wv[TOPK_]; float wsum = 0.f;
        for (int k = 0; k < TOPK_; k++) {
            int best = 0; float bv = p[0];
            for (int e = 1; e < E_; e++) if (p[e] > bv) { bv = p[e]; best = e; }
            idx[k] = best; wv[k] = bv; wsum += bv; p[best] = -1.f;
        }
        float invw = 1.f / wsum;
        for (int k = 0; k < TOPK_; k++) {
            g_topidx[t * TOPK_ + k] = idx[k];
            g_topw[t * TOPK_ + k] = wv[k] * invw;
            atomicAdd(&g_counts[idx[k]], 1);
        }
    }
}

__global__ void k_scan()
{
    int off = 0;
    for (int e = 0; e < E_; e++) {
        g_offsets[e] = off;
        off += g_counts[e];
        g_cursor[e] = 0;
    }
}

__global__ void k_assign()
{
    int i = blockIdx.x * blockDim.x + threadIdx.x;
    if (i >= T_ * TOPK_) return;
    int e = g_topidx[i];
    int slot = g_offsets[e] + atomicAdd(&g_cursor[e], 1);
    g_pair_token[slot] = i >> 2;
    g_pair_slot[i] = slot;
}

// ------- MoE gate_up: BK=16, 3-stage, gate+up packed in ONE B buffer ------------
// B stage = [16][BS_LD]: gate cols [0,64), up cols [64,128). 56.8KB -> 2 CTA/SM.
#define GU_SMEM ((3 * 128 * AS_LD + 3 * 16 * BS_LD) * 4)
__global__ void __launch_bounds__(256) k_gateup(const float* __restrict__ gate_up_w)
{
    extern __shared__ float dsm[];
    float* As = dsm;                                 // [3][128][AS_LD]
    float* Bs = dsm + 3 * 128 * AS_LD;               // [3][16][BS_LD]
    __shared__ int rowTok[128];

    const int e = blockIdx.z;
    const int cnt = g_counts[e];
    const int m0 = blockIdx.y * 128;
    if (m0 >= cnt) return;
    const int base = g_offsets[e];
    const int n0 = blockIdx.x * 64;
    const float* B = gate_up_w + (size_t)e * D_ * (2 * F_);

    const int tid = threadIdx.x, lane = tid & 31, warp = tid >> 5;
    const int wm = warp >> 2, wn = warp & 3;
    const int gid = lane >> 2, tq = lane & 3;

    if (tid < 128) {
        int r = m0 + tid;
        rowTok[tid] = (r < cnt) ? g_pair_token[base + r] : g_pair_token[base];
    }
    __syncthreads();

    const int ar0 = tid >> 1;
    const int ac0 = (tid & 1) * 8;
    const size_t arow = (size_t)rowTok[ar0] * D_;
    const int br0 = tid >> 4;          // 0..15
    const int bc0 = (tid & 15) * 4;    // 0..60

    float ag[4][2][4] = {}, au[4][2][4] = {};

    const int niter = D_ >> 4;
    auto issue = [&](int it) {
        int k0 = it << 4;
        int st = it % 3;
        float* as = As + st * 128 * AS_LD;
        float* bs = Bs + st * 16 * BS_LD;
        cpa16(&as[ar0 * AS_LD + ac0],     &g_h2[arow + k0 + ac0]);
        cpa16(&as[ar0 * AS_LD + ac0 + 4], &g_h2[arow + k0 + ac0 + 4]);
        const float* brow = B + (size_t)(k0 + br0) * (2 * F_);
        cpa16(&bs[br0 * BS_LD + bc0],      &brow[n0 + bc0]);        // gate -> cols [0,64)
        cpa16(&bs[br0 * BS_LD + 64 + bc0], &brow[F_ + n0 + bc0]);   // up   -> cols [64,128)
        cpa_commit();
    };
    issue(0);
    issue(1);

    for (int it = 0; it < niter; it++) {
        if (it + 1 < niter) cpa_wait1(); else cpa_wait0();
        __syncthreads();
        if (it + 2 < niter) issue(it + 2);
        const float* as = As + (it % 3) * 128 * AS_LD;
        const float* bs = Bs + (it % 3) * 16 * BS_LD;
        #pragma unroll
        for (int ks = 0; ks < 16; ks += 8) {
            unsigned a[4][4], bg[2][2], bu[2][2];
            #pragma unroll
            for (int tm = 0; tm < 4; tm++) {
                int r0 = wm * 64 + tm * 16 + gid;
                a[tm][0] = __float_as_uint(as[r0 * AS_LD + ks + tq]);
                a[tm][1] = __float_as_uint(as[(r0 + 8) * AS_LD + ks + tq]);
                a[tm][2] = __float_as_uint(as[r0 * AS_LD + ks + tq + 4]);
                a[tm][3] = __float_as_uint(as[(r0 + 8) * AS_LD + ks + tq + 4]);
            }
            #pragma unroll
            for (int tn = 0; tn < 2; tn++) {
                int c = wn * 16 + tn * 8 + gid;
                bg[tn][0] = __float_as_uint(bs[(ks + tq) * BS_LD + c]);
                bg[tn][1] = __float_as_uint(bs[(ks + tq + 4) * BS_LD + c]);
                bu[tn][0] = __float_as_uint(bs[(ks + tq) * BS_LD + 64 + c]);
                bu[tn][1] = __float_as_uint(bs[(ks + tq + 4) * BS_LD + 64 + c]);
            }
            #pragma unroll
            for (int tm = 0; tm < 4; tm++)
                #pragma unroll
                for (int tn = 0; tn < 2; tn++) {
                    mma_tf32(ag[tm][tn], a[tm], bg[tn]);
                    mma_tf32(au[tm][tn], a[tm], bu[tn]);
                }
        }
    }
    #pragma unroll
    for (int tm = 0; tm < 4; tm++) {
        int r0 = m0 + wm * 64 + tm * 16 + gid;
        int r1 = r0 + 8;
        #pragma unroll
        for (int tn = 0; tn < 2; tn++) {
            int c0 = n0 + wn * 16 + tn * 8 + 2 * tq;
            if (r0 < cnt) {
                float g0 = ag[tm][tn][0], u0 = au[tm][tn][0];
                float g1 = ag[tm][tn][1], u1 = au[tm][tn][1];
                g_gated[(size_t)(base + r0) * F_ + c0]     = u0 * (g0 / (1.f + __expf(-g0)));
                g_gated[(size_t)(base + r0) * F_ + c0 + 1] = u1 * (g1 / (1.f + __expf(-g1)));
            }
            if (r1 < cnt) {
                float g2 = ag[tm][tn][2], u2 = au[tm][tn][2];
                float g3 = ag[tm][tn][3], u3 = au[tm][tn][3];
                g_gated[(size_t)(base + r1) * F_ + c0]     = u2 * (g2 / (1.f + __expf(-g2)));
                g_gated[(size_t)(base + r1) * F_ + c0 + 1] = u3 * (g3 / (1.f + __expf(-g3)));
            }
        }
    }
}

__global__ void __launch_bounds__(256) k_down(const float* __restrict__ down_w)
{
    extern __shared__ float dsm[];
    const int e = blockIdx.z;
    const int cnt = g_counts[e];
    if ((int)blockIdx.y * 128 >= cnt) return;
    const int base = g_offsets[e];
    gemm_tf32_body(dsm, g_gated + (size_t)base * F_, F_,
                   down_w + (size_t)e * F_ * D_, D_,
                   g_pairout + (size_t)base * D_, D_,
                   blockIdx.x * 128, F_, nullptr, cnt);
}

__global__ void k_combine(float* __restrict__ out)
{
    const int t = blockIdx.x;
    const int s0 = g_pair_slot[t * 4 + 0], s1 = g_pair_slot[t * 4 + 1];
    const int s2 = g_pair_slot[t * 4 + 2], s3 = g_pair_slot[t * 4 + 3];
    const float w0 = g_topw[t * 4 + 0], w1 = g_topw[t * 4 + 1];
    const float w2 = g_topw[t * 4 + 2], w3 = g_topw[t * 4 + 3];
    const float* p0 = g_pairout + (size_t)s0 * D_;
    const float* p1 = g_pairout + (size_t)s1 * D_;
    const float* p2 = g_pairout + (size_t)s2 * D_;
    const float* p3 = g_pairout + (size_t)s3 * D_;
    const float* hr = g_hres + (size_t)t * D_;
    float* o = out + (size_t)t * D_;
    for (int d = threadIdx.x; d < D_; d += 256)
        o[d] = hr[d] + w0 * p0[d] + w1 * p1[d] + w2 * p2[d] + w3 * p3[d];
}

// ---------------- launch ----------------
extern "C" void kernel_launch(void* const* d_in, const int* in_sizes, int n_in,
                              void* d_out, int out_size)
{
    const float* hidden = (const float*)d_in[0];
    const float* cosp   = (const float*)d_in[1];
    const float* sinp   = (const float*)d_in[2];
    const float* iln    = (const float*)d_in[4];
    const float* pln    = (const float*)d_in[5];
    const float* qw     = (const float*)d_in[6];
    const float* kw     = (const float*)d_in[7];
    const float* vw     = (const float*)d_in[8];
    const float* ow     = (const float*)d_in[9];
    const float* qnw    = (const float*)d_in[10];
    const float* knw    = (const float*)d_in[11];
    const float* gw     = (const float*)d_in[12];
    const float* guw    = (const float*)d_in[13];
    const float* dw     = (const float*)d_in[14];
    float* out = (float*)d_out;

    static bool attr_set = false;
    if (!attr_set) {
        cudaFuncSetAttribute(k_flashattn, cudaFuncAttributeMaxDynamicSharedMemorySize, FA_SMEM);
        cudaFuncSetAttribute(k_qkv,    cudaFuncAttributeMaxDynamicSharedMemorySize, GEMM_SMEM);
        cudaFuncSetAttribute(k_oproj,  cudaFuncAttributeMaxDynamicSharedMemorySize, GEMM_SMEM);
        cudaFuncSetAttribute(k_down,   cudaFuncAttributeMaxDynamicSharedMemorySize, GEMM_SMEM);
        cudaFuncSetAttribute(k_gateup, cudaFuncAttributeMaxDynamicSharedMemorySize, GU_SMEM);
        attr_set = true;
    }

    k_rmsnorm<<<T_, 256>>>(hidden, iln);
    k_qkv<<<dim3(24, T_ / 128), 256, GEMM_SMEM>>>(qw, kw, vw);
    k_normrope<<<dim3(T_, NQ_ + NKV_), 128>>>(qnw, knw, cosp, sinp);
    k_flashattn<<<dim3(T_ / 32, NKV_, 2), 256, FA_SMEM>>>();
    k_oproj<<<dim3(D_ / 128, T_ / 128), 256, GEMM_SMEM>>>(ow, hidden);
    k_zero<<<1, 32>>>();
    k_rms_router<<<T_, 256>>>(pln, gw);
    k_scan<<<1, 1>>>();
    k_assign<<<(T_ * TOPK_ + 255) / 256, 256>>>();
    k_gateup<<<dim3(F_ / 64, T_ * TOPK_ / 128, E_), 256, GU_SMEM>>>(guw);
    k_down<<<dim3(D_ / 128, T_ * TOPK_ / 128, E_), 256, GEMM_SMEM>>>(dw);
    k_combine<<<T_, 256>>>(out);
}